// round 1
// baseline (speedup 1.0000x reference)
#include <cuda_runtime.h>
#include <math.h>

#define NP 100000
#define NA 50000
#define CDIM 128
#define NH 4
#define NPC (NP*CDIM)
#define NAC (NA*CDIM)
#define EMAX 300000

// ---------------- scratch (device globals: no runtime allocation allowed) ----
__device__ float g_x[2][(NP+NA)*CDIM];      // ping-pong node features (paper | author)
__device__ float g_q[(NP+NA)*CDIM];         // per-layer Q
__device__ float g_krel[3][NPC];            // per edge-type relation-projected K (src-type rows)
__device__ float g_vrel[3][NPC];            // per edge-type relation-projected V
__device__ float g_agg[(NP+NA)*CDIM];       // aggregated messages
__device__ float g_alpha[EMAX*NH];          // per-edge per-head attention scratch
__device__ float g_amax[NP*NH];             // segment max
__device__ float g_den[NP*NH];              // segment sum
__device__ float g_Wk[3][CDIM*CDIM];        // composite K weights  (k_w @ blockdiag(a_rel))
__device__ float g_Wv[3][CDIM*CDIM];        // composite V weights  (v_w @ blockdiag(m_rel))
__device__ float g_bk[3][CDIM];
__device__ float g_bv[3][CDIM];

// ---------------- helpers ----------------------------------------------------
__device__ __forceinline__ float gelu_f(float x) {
    return 0.5f * x * (1.0f + erff(x * 0.7071067811865476f));
}

__device__ __forceinline__ void atomicMaxF(float* addr, float val) {
    if (val >= 0.0f) atomicMax((int*)addr, __float_as_int(val));
    else             atomicMin((unsigned int*)addr, __float_as_uint(val));
}

__global__ void fill_f(float* __restrict__ p, float v, int n) {
    int i = blockIdx.x * blockDim.x + threadIdx.x;
    if (i < n) p[i] = v;
}

// ---------------- composite relation weights ---------------------------------
// Wk[r][c][j] = sum_d k_w[st(r)][c][h*32+d] * a_rel[r][h][d][e],  j = h*32+e
// grid: (CDIM, 3) blocks, 128 threads (thread = output column j)
__global__ void build_comp(const float* __restrict__ kw, const float* __restrict__ kb,
                           const float* __restrict__ vw, const float* __restrict__ vb,
                           const float* __restrict__ arel, const float* __restrict__ mrel,
                           float* __restrict__ Wk, float* __restrict__ bk,
                           float* __restrict__ Wv, float* __restrict__ bv) {
    int c = blockIdx.x, r = blockIdx.y, j = threadIdx.x;
    int st = (r == 1) ? 1 : 0;
    int h = j >> 5, e = j & 31;
    const float* kwp = kw + ((size_t)st * CDIM + c) * CDIM + h * 32;
    const float* vwp = vw + ((size_t)st * CDIM + c) * CDIM + h * 32;
    const float* ap  = arel + (size_t)(r * NH + h) * 1024 + e;   // stride 32 over d
    const float* mp  = mrel + (size_t)(r * NH + h) * 1024 + e;
    float sk = 0.f, sv = 0.f;
#pragma unroll
    for (int d = 0; d < 32; d++) {
        sk += kwp[d] * ap[d * 32];
        sv += vwp[d] * mp[d * 32];
    }
    Wk[(size_t)r * CDIM * CDIM + (size_t)c * CDIM + j] = sk;
    Wv[(size_t)r * CDIM * CDIM + (size_t)c * CDIM + j] = sv;
    if (c == 0) {
        float bks = 0.f, bvs = 0.f;
        const float* kbp = kb + st * CDIM + h * 32;
        const float* vbp = vb + st * CDIM + h * 32;
#pragma unroll
        for (int d = 0; d < 32; d++) {
            bks += kbp[d] * ap[d * 32];
            bvs += vbp[d] * mp[d * 32];
        }
        bk[r * CDIM + j] = bks;
        bv[r * CDIM + j] = bvs;
    }
}

// ---------------- tiled fp32 GEMM: out[M,128] = f(A)[M,128] @ W[128,128] -----
// aop: 0 none, 1 gelu(A element-wise)
// eop: 0 +bias, 1 +bias,relu, 2 skip-blend: sig(skip)*(acc+bias)+(1-sig)*xold
__global__ void __launch_bounds__(256)
gemm_nk128(const float* __restrict__ A, const float* __restrict__ W,
           const float* __restrict__ bias, float* __restrict__ Out,
           int M, int aop, int eop,
           const float* __restrict__ xold, const float* __restrict__ skip_ptr) {
    __shared__ float As[16][132];   // [k][m], padded row stride (528B, 16B-aligned)
    __shared__ float Bs[16][128];   // [k][n]
    int tid = threadIdx.x;
    int tx = tid & 15, ty = tid >> 4;            // tn = tx*8, tm = ty*8
    int tm = ty * 8, tn = tx * 8;
    int rowBase = blockIdx.x * 128;

    float acc[8][8];
#pragma unroll
    for (int i = 0; i < 8; i++)
#pragma unroll
        for (int j = 0; j < 8; j++) acc[i][j] = 0.f;

    for (int k0 = 0; k0 < 128; k0 += 16) {
        // load A chunk (128 rows x 16 k), transpose into As[k][m]
#pragma unroll
        for (int jj = 0; jj < 2; jj++) {
            int fl = tid + jj * 256;             // 0..511 float4s
            int m = fl >> 2, kq = fl & 3;
            int row = rowBase + m;
            float4 v = make_float4(0.f, 0.f, 0.f, 0.f);
            if (row < M)
                v = *(const float4*)(A + (size_t)row * CDIM + k0 + kq * 4);
            if (aop) { v.x = gelu_f(v.x); v.y = gelu_f(v.y); v.z = gelu_f(v.z); v.w = gelu_f(v.w); }
            As[kq * 4 + 0][m] = v.x;
            As[kq * 4 + 1][m] = v.y;
            As[kq * 4 + 2][m] = v.z;
            As[kq * 4 + 3][m] = v.w;
        }
        // load B chunk (16 k x 128 n)
#pragma unroll
        for (int jj = 0; jj < 2; jj++) {
            int fl = tid + jj * 256;
            int kr = fl >> 5, nc = (fl & 31) * 4;
            *(float4*)&Bs[kr][nc] = *(const float4*)(W + (size_t)(k0 + kr) * CDIM + nc);
        }
        __syncthreads();
#pragma unroll
        for (int k = 0; k < 16; k++) {
            float a[8], b[8];
            *(float4*)(a)     = *(float4*)&As[k][tm];
            *(float4*)(a + 4) = *(float4*)&As[k][tm + 4];
            *(float4*)(b)     = *(float4*)&Bs[k][tn];
            *(float4*)(b + 4) = *(float4*)&Bs[k][tn + 4];
#pragma unroll
            for (int i = 0; i < 8; i++)
#pragma unroll
                for (int j = 0; j < 8; j++) acc[i][j] += a[i] * b[j];
        }
        __syncthreads();
    }

    float bj[8];
#pragma unroll
    for (int j = 0; j < 8; j++) bj[j] = bias[tn + j];
    float sk = 0.f;
    if (eop == 2) sk = 1.f / (1.f + expf(-*skip_ptr));

#pragma unroll
    for (int i = 0; i < 8; i++) {
        int row = rowBase + tm + i;
        if (row >= M) break;
        float v[8];
#pragma unroll
        for (int j = 0; j < 8; j++) v[j] = acc[i][j] + bj[j];
        if (eop == 1) {
#pragma unroll
            for (int j = 0; j < 8; j++) v[j] = fmaxf(v[j], 0.f);
        } else if (eop == 2) {
            float xo[8];
            *(float4*)(xo)     = *(const float4*)(xold + (size_t)row * CDIM + tn);
            *(float4*)(xo + 4) = *(const float4*)(xold + (size_t)row * CDIM + tn + 4);
#pragma unroll
            for (int j = 0; j < 8; j++) v[j] = sk * v[j] + (1.f - sk) * xo[j];
        }
        *(float4*)(Out + (size_t)row * CDIM + tn)     = *(float4*)(v);
        *(float4*)(Out + (size_t)row * CDIM + tn + 4) = *(float4*)(v + 4);
    }
}

// ---------------- edge kernels ------------------------------------------------
// thread = (edge, head)
__global__ void edge_alpha(const float* __restrict__ q, const float* __restrict__ kr,
                           const int* __restrict__ src, const int* __restrict__ dst,
                           const float* __restrict__ prel,
                           float* __restrict__ alpha, float* __restrict__ amax, int E) {
    int idx = blockIdx.x * blockDim.x + threadIdx.x;
    int e = idx >> 2;
    if (e >= E) return;
    int h = idx & 3;
    int s = src[e], d = dst[e];
    const float4* qa = (const float4*)(q  + (size_t)d * CDIM + h * 32);
    const float4* ka = (const float4*)(kr + (size_t)s * CDIM + h * 32);
    float sum = 0.f;
#pragma unroll
    for (int i = 0; i < 8; i++) {
        float4 a = qa[i], b = ka[i];
        sum += a.x * b.x + a.y * b.y + a.z * b.z + a.w * b.w;
    }
    sum *= prel[h] * 0.17677669529663687f;   // / sqrt(32)
    alpha[idx] = sum;
    atomicMaxF(&amax[(size_t)d * NH + h], sum);
}

__global__ void edge_exp(const int* __restrict__ dst, const float* __restrict__ amax,
                         float* __restrict__ alpha, float* __restrict__ den, int E) {
    int idx = blockIdx.x * blockDim.x + threadIdx.x;
    int e = idx >> 2;
    if (e >= E) return;
    int h = idx & 3;
    int d = dst[e];
    float ex = expf(alpha[idx] - amax[(size_t)d * NH + h]);
    alpha[idx] = ex;
    atomicAdd(&den[(size_t)d * NH + h], ex);
}

// thread = (edge, float4-chunk): 32 threads per edge
__global__ void edge_scatter(const float* __restrict__ vrel,
                             const int* __restrict__ src, const int* __restrict__ dst,
                             const float* __restrict__ alpha, const float* __restrict__ den,
                             float* __restrict__ agg, int E) {
    int idx = blockIdx.x * blockDim.x + threadIdx.x;
    int e = idx >> 5;
    if (e >= E) return;
    int t = idx & 31;
    int h = t >> 3;
    int s = src[e], d = dst[e];
    float w = alpha[(size_t)e * NH + h] / (den[(size_t)d * NH + h] + 1e-16f);
    float4 v = *(const float4*)(vrel + (size_t)s * CDIM + t * 4);
    float* o = agg + (size_t)d * CDIM + t * 4;
    atomicAdd(o + 0, w * v.x);
    atomicAdd(o + 1, w * v.y);
    atomicAdd(o + 2, w * v.z);
    atomicAdd(o + 3, w * v.w);
}

// ---------------- host orchestration ------------------------------------------
extern "C" void kernel_launch(void* const* d_in, const int* in_sizes, int n_in,
                              void* d_out, int out_size) {
    const float* x_paper  = (const float*)d_in[0];
    const float* x_author = (const float*)d_in[1];
    const float* lin_w = (const float*)d_in[2];
    const float* lin_b = (const float*)d_in[3];
    const float* k_w = (const float*)d_in[4];
    const float* k_b = (const float*)d_in[5];
    const float* q_w = (const float*)d_in[6];
    const float* q_b = (const float*)d_in[7];
    const float* v_w = (const float*)d_in[8];
    const float* v_b = (const float*)d_in[9];
    const float* a_w = (const float*)d_in[10];
    const float* a_b = (const float*)d_in[11];
    const float* skip  = (const float*)d_in[12];
    const float* a_rel = (const float*)d_in[13];
    const float* m_rel = (const float*)d_in[14];
    const float* p_rel = (const float*)d_in[15];
    const int* srcs[3] = {(const int*)d_in[16], (const int*)d_in[18], (const int*)d_in[20]};
    const int* dsts[3] = {(const int*)d_in[17], (const int*)d_in[19], (const int*)d_in[21]};
    int E[3] = {in_sizes[16], in_sizes[18], in_sizes[20]};

    void* p;
    float *xb[2], *qb, *krel, *vrel, *agg, *alpha, *amax, *den, *Wk, *Wv, *bk, *bv;
    cudaGetSymbolAddress(&p, g_x);    xb[0] = (float*)p; xb[1] = xb[0] + (size_t)(NP + NA) * CDIM;
    cudaGetSymbolAddress(&p, g_q);    qb    = (float*)p;
    cudaGetSymbolAddress(&p, g_krel); krel  = (float*)p;
    cudaGetSymbolAddress(&p, g_vrel); vrel  = (float*)p;
    cudaGetSymbolAddress(&p, g_agg);  agg   = (float*)p;
    cudaGetSymbolAddress(&p, g_alpha);alpha = (float*)p;
    cudaGetSymbolAddress(&p, g_amax); amax  = (float*)p;
    cudaGetSymbolAddress(&p, g_den);  den   = (float*)p;
    cudaGetSymbolAddress(&p, g_Wk);   Wk    = (float*)p;
    cudaGetSymbolAddress(&p, g_Wv);   Wv    = (float*)p;
    cudaGetSymbolAddress(&p, g_bk);   bk    = (float*)p;
    cudaGetSymbolAddress(&p, g_bv);   bv    = (float*)p;

    auto gemm = [&](const float* A, const float* W, const float* b, float* O, int M,
                    int aop, int eop, const float* xold, const float* sp) {
        gemm_nk128<<<(M + 127) / 128, 256>>>(A, W, b, O, M, aop, eop, xold, sp);
    };

    // wrapper: per-type linear + relu
    gemm(x_paper,  lin_w,               lin_b,        xb[0],       NP, 0, 1, nullptr, nullptr);
    gemm(x_author, lin_w + CDIM * CDIM, lin_b + CDIM, xb[0] + NPC, NA, 0, 1, nullptr, nullptr);

    int cur = 0;
    for (int l = 0; l < 2; l++) {
        // composite relation weights for this layer
        build_comp<<<dim3(CDIM, 3), CDIM>>>(
            k_w + (size_t)l * 2 * CDIM * CDIM, k_b + l * 2 * CDIM,
            v_w + (size_t)l * 2 * CDIM * CDIM, v_b + l * 2 * CDIM,
            a_rel + (size_t)l * 3 * NH * 1024, m_rel + (size_t)l * 3 * NH * 1024,
            Wk, bk, Wv, bv);

        // Q per node type
        gemm(xb[cur],       q_w + (size_t)(l * 2 + 0) * CDIM * CDIM, q_b + (l * 2 + 0) * CDIM, qb,       NP, 0, 0, nullptr, nullptr);
        gemm(xb[cur] + NPC, q_w + (size_t)(l * 2 + 1) * CDIM * CDIM, q_b + (l * 2 + 1) * CDIM, qb + NPC, NA, 0, 0, nullptr, nullptr);

        // relation-projected K/V directly from x via composite weights
        for (int r = 0; r < 3; r++) {
            int st = (r == 1) ? 1 : 0;
            int sN = st ? NA : NP;
            const float* xs = xb[cur] + (st ? NPC : 0);
            gemm(xs, Wk + (size_t)r * CDIM * CDIM, bk + r * CDIM, krel + (size_t)r * NPC, sN, 0, 0, nullptr, nullptr);
            gemm(xs, Wv + (size_t)r * CDIM * CDIM, bv + r * CDIM, vrel + (size_t)r * NPC, sN, 0, 0, nullptr, nullptr);
        }

        // zero aggregation buffers
        {
            int n = (NP + NA) * CDIM;
            fill_f<<<(n + 255) / 256, 256>>>(agg, 0.f, n);
        }

        // edge phase, per edge type (softmax is per-type)
        for (int r = 0; r < 3; r++) {
            int dt = (r == 2) ? 1 : 0;
            int dN = dt ? NA : NP;
            int nm = dN * NH;
            fill_f<<<(nm + 255) / 256, 256>>>(amax, -INFINITY, nm);
            fill_f<<<(nm + 255) / 256, 256>>>(den, 0.f, nm);
            int nt = E[r] * NH;
            const float* qbase = qb + (dt ? NPC : 0);
            edge_alpha<<<(nt + 255) / 256, 256>>>(qbase, krel + (size_t)r * NPC,
                                                  srcs[r], dsts[r],
                                                  p_rel + (size_t)(l * 3 + r) * NH,
                                                  alpha, amax, E[r]);
            edge_exp<<<(nt + 255) / 256, 256>>>(dsts[r], amax, alpha, den, E[r]);
            int nt2 = E[r] * 32;
            edge_scatter<<<(nt2 + 255) / 256, 256>>>(vrel + (size_t)r * NPC,
                                                     srcs[r], dsts[r], alpha, den,
                                                     agg + (dt ? NPC : 0), E[r]);
        }

        // output projection: gelu(agg) @ a_w + a_b, skip-blend; last layer -> d_out
        for (int t = 0; t < 2; t++) {
            int Mt = t ? NA : NP;
            size_t off = t ? (size_t)NPC : 0;
            float* outp = (l == 1) ? ((float*)d_out + off) : (xb[1 - cur] + off);
            gemm(agg + off, a_w + (size_t)(l * 2 + t) * CDIM * CDIM, a_b + (l * 2 + t) * CDIM,
                 outp, Mt, 1, 2, xb[cur] + off, skip + l * 2 + t);
        }
        cur = 1 - cur;
    }
}

// round 3
// speedup vs baseline: 1.1779x; 1.1779x over previous
#include <cuda_runtime.h>
#include <cuda_bf16.h>
#include <math.h>
#include <stdint.h>

#define NP 100000
#define NA 50000
#define CDIM 128
#define CC (CDIM*CDIM)
#define NH 4
#define NPC (NP*CDIM)
#define EMAX 300000

#define PITCH 136                 // bf16 elements per row in staged images
#define PITCHB 272                // bytes
#define IMG_B16 (128*PITCH)       // 17408 bf16 per image
#define IMG_BYTES (IMG_B16*2)     // 34816 bytes
#define SLOT_U32 (IMG_B16)        // hi+lo = 2 images = 17408 u32 per slot

// ---------------- scratch (device globals) -----------------------------------
__device__ float g_x[2][(NP+NA)*CDIM];
__device__ float g_q[(NP+NA)*CDIM];
__device__ float g_krel[3][NPC];
__device__ float g_vrel[3][NPC];
__device__ float g_agg[(NP+NA)*CDIM];
__device__ float g_alpha[EMAX*NH];
__device__ float g_amax[NP*NH];
__device__ float g_den[NP*NH];
__device__ float g_Wk[3][CC];
__device__ float g_Wv[3][CC];
__device__ float g_bk[3][CDIM];
__device__ float g_bv[3][CDIM];
__device__ uint32_t g_wpack[10][SLOT_U32];   // per slot: hi image then lo image (pitched)

// ---------------- small helpers ----------------------------------------------
__device__ __forceinline__ float gelu_f(float x) {
    return 0.5f * x * (1.0f + erff(x * 0.7071067811865476f));
}
__device__ __forceinline__ void atomicMaxF(float* addr, float val) {
    if (val >= 0.0f) atomicMax((int*)addr, __float_as_int(val));
    else             atomicMin((unsigned int*)addr, __float_as_uint(val));
}
__global__ void fill_f(float* __restrict__ p, float v, int n) {
    int i = blockIdx.x * blockDim.x + threadIdx.x;
    if (i < n) p[i] = v;
}
__device__ __forceinline__ uint32_t smem_u32(const void* p) {
    uint32_t a;
    asm("{ .reg .u64 t; cvta.to.shared.u64 t, %1; cvt.u32.u64 %0, t; }" : "=r"(a) : "l"(p));
    return a;
}
__device__ __forceinline__ uint32_t pk_bf2(__nv_bfloat16 a, __nv_bfloat16 b) {
    __nv_bfloat162 t = __halves2bfloat162(a, b);
    return *reinterpret_cast<uint32_t*>(&t);
}
__device__ __forceinline__ void ldsm4(uint32_t* r, uint32_t addr) {
    asm volatile("ldmatrix.sync.aligned.m8n8.x4.shared.b16 {%0,%1,%2,%3}, [%4];"
        : "=r"(r[0]), "=r"(r[1]), "=r"(r[2]), "=r"(r[3]) : "r"(addr));
}
__device__ __forceinline__ void mma16816(float* c, const uint32_t* a, const uint32_t* b) {
    asm volatile("mma.sync.aligned.m16n8k16.row.col.f32.bf16.bf16.f32 "
        "{%0,%1,%2,%3}, {%4,%5,%6,%7}, {%8,%9}, {%0,%1,%2,%3};"
        : "+f"(c[0]), "+f"(c[1]), "+f"(c[2]), "+f"(c[3])
        : "r"(a[0]), "r"(a[1]), "r"(a[2]), "r"(a[3]), "r"(b[0]), "r"(b[1]));
}

// ---------------- weight packing: fp32 [128k x 128n] -> pitched bf16 hi/lo ----
// image layout: img[n*PITCH + k] (B stored n-major, k contiguous = col-major B)
struct PackSrc { const float* w[10]; int count; };
__global__ void pack_weights(PackSrc ps, uint32_t* dstbase) {
    int m = blockIdx.x;
    if (m >= ps.count) return;
    const float* W = ps.w[m];
    uint32_t* hi = dstbase + (size_t)m * SLOT_U32;
    uint32_t* lo = hi + IMG_B16 / 2;
    int n = threadIdx.x;
    for (int k = 0; k < 128; k += 2) {
        float a0 = W[k * 128 + n], a1 = W[(k + 1) * 128 + n];
        __nv_bfloat16 h0 = __float2bfloat16(a0), h1 = __float2bfloat16(a1);
        float r0 = a0 - __bfloat162float(h0), r1 = a1 - __bfloat162float(h1);
        int idx = n * (PITCH / 2) + (k >> 1);
        hi[idx] = pk_bf2(h0, h1);
        lo[idx] = pk_bf2(__float2bfloat16(r0), __float2bfloat16(r1));
    }
}

// ---------------- composite relation weights ----------------------------------
__global__ void build_comp(const float* __restrict__ kw, const float* __restrict__ kb,
                           const float* __restrict__ vw, const float* __restrict__ vb,
                           const float* __restrict__ arel, const float* __restrict__ mrel,
                           float* __restrict__ Wk, float* __restrict__ bk,
                           float* __restrict__ Wv, float* __restrict__ bv) {
    int c = blockIdx.x, r = blockIdx.y, j = threadIdx.x;
    int st = (r == 1) ? 1 : 0;
    int h = j >> 5, e = j & 31;
    const float* kwp = kw + ((size_t)st * CDIM + c) * CDIM + h * 32;
    const float* vwp = vw + ((size_t)st * CDIM + c) * CDIM + h * 32;
    const float* ap  = arel + (size_t)(r * NH + h) * 1024 + e;
    const float* mp  = mrel + (size_t)(r * NH + h) * 1024 + e;
    float sk = 0.f, sv = 0.f;
#pragma unroll
    for (int d = 0; d < 32; d++) {
        sk += kwp[d] * ap[d * 32];
        sv += vwp[d] * mp[d * 32];
    }
    Wk[(size_t)r * CC + (size_t)c * CDIM + j] = sk;
    Wv[(size_t)r * CC + (size_t)c * CDIM + j] = sv;
    if (c == 0) {
        float bks = 0.f, bvs = 0.f;
        const float* kbp = kb + st * CDIM + h * 32;
        const float* vbp = vb + st * CDIM + h * 32;
#pragma unroll
        for (int d = 0; d < 32; d++) {
            bks += kbp[d] * ap[d * 32];
            bvs += vbp[d] * mp[d * 32];
        }
        bk[r * CDIM + j] = bks;
        bv[r * CDIM + j] = bvs;
    }
}

// ---------------- tensor-core GEMM (mma.sync bf16, 3-term hi/lo split) --------
// C[M, 128 per tile] = f(A)[M,128] @ {W_b}[128,128]
// aop: 0 none, 1 gelu(A); eop: 0 +bias, 1 +bias+relu, 2 skip-blend
struct TileArgs {
    const uint4* wp[5];     // packed pitched (hi|lo) images, IMG_BYTES*2 each
    const float* bias[5];
    float*       out[5];
};

#define SM_A_HI  0
#define SM_A_LO  IMG_BYTES
#define SM_B_HI  (2*IMG_BYTES)
#define SM_B_LO  (3*IMG_BYTES)
#define SM_NEED  (4*IMG_BYTES)          // 139264 bytes

__global__ void __launch_bounds__(256, 1)
gemm_mma(const float* __restrict__ A, TileArgs ta, int ntiles, int M,
         int aop, int eop, const float* __restrict__ xold, const float* __restrict__ skipp) {
    extern __shared__ char sm[];
    uint32_t sb = smem_u32(sm);
    int tid = threadIdx.x, lane = tid & 31, wid = tid >> 5;
    int wm = wid & 3, wn = wid >> 2;           // 4 m-warps x 2 n-warps
    int rowBase = blockIdx.x * 128;

    // ---- stage A: fp32 -> gelu? -> bf16 hi/lo, pitched ----
#pragma unroll 4
    for (int it = 0; it < 16; it++) {
        int f = it * 256 + tid;                // 4096 float4 chunks
        int m = f >> 5, k = (f & 31) << 2;
        int row = rowBase + m;
        float4 v = make_float4(0.f, 0.f, 0.f, 0.f);
        if (row < M) v = *(const float4*)(A + (size_t)row * CDIM + k);
        if (aop) { v.x = gelu_f(v.x); v.y = gelu_f(v.y); v.z = gelu_f(v.z); v.w = gelu_f(v.w); }
        __nv_bfloat16 h0 = __float2bfloat16(v.x), h1 = __float2bfloat16(v.y);
        __nv_bfloat16 h2 = __float2bfloat16(v.z), h3 = __float2bfloat16(v.w);
        float r0 = v.x - __bfloat162float(h0), r1 = v.y - __bfloat162float(h1);
        float r2 = v.z - __bfloat162float(h2), r3 = v.w - __bfloat162float(h3);
        uint32_t off = (uint32_t)(m * PITCHB + k * 2);
        *(uint2*)(sm + SM_A_HI + off) = make_uint2(pk_bf2(h0, h1), pk_bf2(h2, h3));
        *(uint2*)(sm + SM_A_LO + off) = make_uint2(
            pk_bf2(__float2bfloat16(r0), __float2bfloat16(r1)),
            pk_bf2(__float2bfloat16(r2), __float2bfloat16(r3)));
    }

    // ldmatrix base addresses
    int aRow = wm * 32 + (lane & 15);
    uint32_t aKoff = (lane & 16) ? 16u : 0u;                 // +8 b16
    uint32_t aBaseHi = sb + SM_A_HI + aRow * PITCHB + aKoff;
    uint32_t aBaseLo = aBaseHi + IMG_BYTES;
    int bN = wn * 64 + (lane & 7) + ((lane & 16) ? 8 : 0);
    uint32_t bKoff = (lane & 8) ? 16u : 0u;
    uint32_t bBaseHi = sb + SM_B_HI + bN * PITCHB + bKoff;
    uint32_t bBaseLo = bBaseHi + IMG_BYTES;

    float skv = 0.f;
    if (eop == 2) skv = 1.f / (1.f + expf(-*skipp));
    int g = lane >> 2, tg = lane & 3;

    for (int b = 0; b < ntiles; b++) {
        __syncthreads();        // A ready (first iter) / prior ldmatrix done
        // ---- stage B: linear copy of pre-packed 68KB (hi|lo) ----
        const uint4* src = ta.wp[b];
        uint4* dB = (uint4*)(sm + SM_B_HI);
#pragma unroll
        for (int i = 0; i < 17; i++) dB[i * 256 + tid] = src[i * 256 + tid];
        __syncthreads();

        float acc[2][8][4];
#pragma unroll
        for (int i = 0; i < 2; i++)
#pragma unroll
            for (int j = 0; j < 8; j++)
#pragma unroll
                for (int q = 0; q < 4; q++) acc[i][j][q] = 0.f;

        uint32_t aHi = aBaseHi, aLo = aBaseLo, bHi = bBaseHi, bLo = bBaseLo;
#pragma unroll
        for (int ks = 0; ks < 8; ks++) {
            uint32_t ah[2][4], al[2][4], bb[4][4];
            ldsm4(ah[0], aHi); ldsm4(ah[1], aHi + 16 * PITCHB);
            ldsm4(al[0], aLo); ldsm4(al[1], aLo + 16 * PITCHB);
#pragma unroll
            for (int jp = 0; jp < 4; jp++) ldsm4(bb[jp], bHi + jp * 16 * PITCHB);
#pragma unroll
            for (int i = 0; i < 2; i++)
#pragma unroll
                for (int j = 0; j < 8; j++) {
                    const uint32_t* bp = &bb[j >> 1][(j & 1) * 2];
                    mma16816(acc[i][j], ah[i], bp);
                    mma16816(acc[i][j], al[i], bp);
                }
#pragma unroll
            for (int jp = 0; jp < 4; jp++) ldsm4(bb[jp], bLo + jp * 16 * PITCHB);
#pragma unroll
            for (int i = 0; i < 2; i++)
#pragma unroll
                for (int j = 0; j < 8; j++)
                    mma16816(acc[i][j], ah[i], &bb[j >> 1][(j & 1) * 2]);
            aHi += 32; aLo += 32; bHi += 32; bLo += 32;
        }

        // ---- epilogue: regs -> gmem with bias / relu / skip-blend ----
        const float* bias = ta.bias[b];
        float* out = ta.out[b];
#pragma unroll
        for (int i = 0; i < 2; i++) {
            int r0 = rowBase + wm * 32 + i * 16 + g;
#pragma unroll
            for (int j = 0; j < 8; j++) {
                int col = wn * 64 + j * 8 + tg * 2;
                float b0 = bias[col], b1 = bias[col + 1];
#pragma unroll
                for (int half = 0; half < 2; half++) {
                    int row = r0 + half * 8;
                    if (row >= M) continue;
                    float v0 = acc[i][j][half * 2 + 0] + b0;
                    float v1 = acc[i][j][half * 2 + 1] + b1;
                    if (eop == 1) {
                        v0 = fmaxf(v0, 0.f); v1 = fmaxf(v1, 0.f);
                    } else if (eop == 2) {
                        float2 xo = *(const float2*)(xold + (size_t)row * CDIM + col);
                        v0 = skv * v0 + (1.f - skv) * xo.x;
                        v1 = skv * v1 + (1.f - skv) * xo.y;
                    }
                    *(float2*)(out + (size_t)row * CDIM + col) = make_float2(v0, v1);
                }
            }
        }
    }
}

// ---------------- edge kernels -------------------------------------------------
__global__ void edge_alpha(const float* __restrict__ q, const float* __restrict__ kr,
                           const int* __restrict__ src, const int* __restrict__ dst,
                           const float* __restrict__ prel,
                           float* __restrict__ alpha, float* __restrict__ amax, int E) {
    int idx = blockIdx.x * blockDim.x + threadIdx.x;
    int e = idx >> 2;
    if (e >= E) return;
    int h = idx & 3;
    int s = src[e], d = dst[e];
    const float4* qa = (const float4*)(q  + (size_t)d * CDIM + h * 32);
    const float4* ka = (const float4*)(kr + (size_t)s * CDIM + h * 32);
    float sum = 0.f;
#pragma unroll
    for (int i = 0; i < 8; i++) {
        float4 a = qa[i], b = ka[i];
        sum += a.x * b.x + a.y * b.y + a.z * b.z + a.w * b.w;
    }
    sum *= prel[h] * 0.17677669529663687f;
    alpha[idx] = sum;
    atomicMaxF(&amax[(size_t)d * NH + h], sum);
}

__global__ void edge_exp(const int* __restrict__ dst, const float* __restrict__ amax,
                         float* __restrict__ alpha, float* __restrict__ den, int E) {
    int idx = blockIdx.x * blockDim.x + threadIdx.x;
    int e = idx >> 2;
    if (e >= E) return;
    int h = idx & 3;
    int d = dst[e];
    float ex = expf(alpha[idx] - amax[(size_t)d * NH + h]);
    alpha[idx] = ex;
    atomicAdd(&den[(size_t)d * NH + h], ex);
}

__global__ void edge_scatter(const float* __restrict__ vrel,
                             const int* __restrict__ src, const int* __restrict__ dst,
                             const float* __restrict__ alpha, const float* __restrict__ den,
                             float* __restrict__ agg, int E) {
    int idx = blockIdx.x * blockDim.x + threadIdx.x;
    int e = idx >> 5;
    if (e >= E) return;
    int t = idx & 31;
    int h = t >> 3;
    int s = src[e], d = dst[e];
    float w = alpha[(size_t)e * NH + h] / (den[(size_t)d * NH + h] + 1e-16f);
    float4 v = *(const float4*)(vrel + (size_t)s * CDIM + t * 4);
    float* o = agg + (size_t)d * CDIM + t * 4;
    atomicAdd(o + 0, w * v.x);
    atomicAdd(o + 1, w * v.y);
    atomicAdd(o + 2, w * v.z);
    atomicAdd(o + 3, w * v.w);
}

// ---------------- host orchestration -------------------------------------------
extern "C" void kernel_launch(void* const* d_in, const int* in_sizes, int n_in,
                              void* d_out, int out_size) {
    const float* x_paper  = (const float*)d_in[0];
    const float* x_author = (const float*)d_in[1];
    const float* lin_w = (const float*)d_in[2];
    const float* lin_b = (const float*)d_in[3];
    const float* k_w = (const float*)d_in[4];
    const float* k_b = (const float*)d_in[5];
    const float* q_w = (const float*)d_in[6];
    const float* q_b = (const float*)d_in[7];
    const float* v_w = (const float*)d_in[8];
    const float* v_b = (const float*)d_in[9];
    const float* a_w = (const float*)d_in[10];
    const float* a_b = (const float*)d_in[11];
    const float* skip  = (const float*)d_in[12];
    const float* a_rel = (const float*)d_in[13];
    const float* m_rel = (const float*)d_in[14];
    const float* p_rel = (const float*)d_in[15];
    const int* srcs[3] = {(const int*)d_in[16], (const int*)d_in[18], (const int*)d_in[20]};
    const int* dsts[3] = {(const int*)d_in[17], (const int*)d_in[19], (const int*)d_in[21]};
    int E[3] = {in_sizes[16], in_sizes[18], in_sizes[20]};

    cudaFuncSetAttribute(gemm_mma, cudaFuncAttributeMaxDynamicSharedMemorySize, SM_NEED);

    void* p;
    float *xb[2], *qb, *krel, *vrel, *agg, *alpha, *amax, *den, *Wk, *Wv, *bk, *bv;
    uint32_t* wpack;
    cudaGetSymbolAddress(&p, g_x);    xb[0] = (float*)p; xb[1] = xb[0] + (size_t)(NP + NA) * CDIM;
    cudaGetSymbolAddress(&p, g_q);    qb    = (float*)p;
    cudaGetSymbolAddress(&p, g_krel); krel  = (float*)p;
    cudaGetSymbolAddress(&p, g_vrel); vrel  = (float*)p;
    cudaGetSymbolAddress(&p, g_agg);  agg   = (float*)p;
    cudaGetSymbolAddress(&p, g_alpha);alpha = (float*)p;
    cudaGetSymbolAddress(&p, g_amax); amax  = (float*)p;
    cudaGetSymbolAddress(&p, g_den);  den   = (float*)p;
    cudaGetSymbolAddress(&p, g_Wk);   Wk    = (float*)p;
    cudaGetSymbolAddress(&p, g_Wv);   Wv    = (float*)p;
    cudaGetSymbolAddress(&p, g_bk);   bk    = (float*)p;
    cudaGetSymbolAddress(&p, g_bv);   bv    = (float*)p;
    cudaGetSymbolAddress(&p, g_wpack);wpack = (uint32_t*)p;

    auto slot = [&](int s) { return (const uint4*)(wpack + (size_t)s * SLOT_U32); };
    auto run_gemm = [&](const float* A, TileArgs& ta, int nt, int M, int aop, int eop,
                        const float* xold, const float* sp) {
        gemm_mma<<<(M + 127) / 128, 256, SM_NEED>>>(A, ta, nt, M, aop, eop, xold, sp);
    };

    // ---- wrapper: pack lin_w (slots 0,1), per-type linear + relu ----
    {
        PackSrc ps{};
        ps.w[0] = lin_w; ps.w[1] = lin_w + CC; ps.count = 2;
        pack_weights<<<2, 128>>>(ps, wpack);
        TileArgs ta{};
        ta.wp[0] = slot(0); ta.bias[0] = lin_b; ta.out[0] = xb[0];
        run_gemm(x_paper, ta, 1, NP, 0, 1, nullptr, nullptr);
        ta.wp[0] = slot(1); ta.bias[0] = lin_b + CDIM; ta.out[0] = xb[0] + NPC;
        run_gemm(x_author, ta, 1, NA, 0, 1, nullptr, nullptr);
    }

    int cur = 0;
    for (int l = 0; l < 2; l++) {
        build_comp<<<dim3(CDIM, 3), CDIM>>>(
            k_w + (size_t)l * 2 * CC, k_b + l * 2 * CDIM,
            v_w + (size_t)l * 2 * CC, v_b + l * 2 * CDIM,
            a_rel + (size_t)l * 3 * NH * 1024, m_rel + (size_t)l * 3 * NH * 1024,
            Wk, bk, Wv, bv);

        // slots: 0:q_p 1:q_a 2:Wk0 3:Wv0 4:Wk2 5:Wv2 6:Wk1 7:Wv1 8:aw_p 9:aw_a
        {
            PackSrc ps{};
            ps.w[0] = q_w + (size_t)(l * 2 + 0) * CC;
            ps.w[1] = q_w + (size_t)(l * 2 + 1) * CC;
            ps.w[2] = Wk;          ps.w[3] = Wv;
            ps.w[4] = Wk + 2 * CC; ps.w[5] = Wv + 2 * CC;
            ps.w[6] = Wk + CC;     ps.w[7] = Wv + CC;
            ps.w[8] = a_w + (size_t)(l * 2 + 0) * CC;
            ps.w[9] = a_w + (size_t)(l * 2 + 1) * CC;
            ps.count = 10;
            pack_weights<<<10, 128>>>(ps, wpack);
        }

        // fused GEMM over paper source: q_p | krel0 | vrel0 | krel2 | vrel2
        {
            TileArgs ta{};
            ta.wp[0] = slot(0); ta.bias[0] = q_b + (l * 2 + 0) * CDIM; ta.out[0] = qb;
            ta.wp[1] = slot(2); ta.bias[1] = bk;             ta.out[1] = krel;
            ta.wp[2] = slot(3); ta.bias[2] = bv;             ta.out[2] = vrel;
            ta.wp[3] = slot(4); ta.bias[3] = bk + 2 * CDIM;  ta.out[3] = krel + 2 * (size_t)NPC;
            ta.wp[4] = slot(5); ta.bias[4] = bv + 2 * CDIM;  ta.out[4] = vrel + 2 * (size_t)NPC;
            run_gemm(xb[cur], ta, 5, NP, 0, 0, nullptr, nullptr);
        }
        // fused GEMM over author source: q_a | krel1 | vrel1
        {
            TileArgs ta{};
            ta.wp[0] = slot(1); ta.bias[0] = q_b + (l * 2 + 1) * CDIM; ta.out[0] = qb + NPC;
            ta.wp[1] = slot(6); ta.bias[1] = bk + CDIM;      ta.out[1] = krel + (size_t)NPC;
            ta.wp[2] = slot(7); ta.bias[2] = bv + CDIM;      ta.out[2] = vrel + (size_t)NPC;
            run_gemm(xb[cur] + NPC, ta, 3, NA, 0, 0, nullptr, nullptr);
        }

        {
            int n = (NP + NA) * CDIM;
            fill_f<<<(n + 255) / 256, 256>>>(agg, 0.f, n);
        }

        for (int r = 0; r < 3; r++) {
            int dt = (r == 2) ? 1 : 0;
            int dN = dt ? NA : NP;
            int nm = dN * NH;
            fill_f<<<(nm + 255) / 256, 256>>>(amax, -INFINITY, nm);
            fill_f<<<(nm + 255) / 256, 256>>>(den, 0.f, nm);
            int nt = E[r] * NH;
            const float* qbase = qb + (dt ? NPC : 0);
            edge_alpha<<<(nt + 255) / 256, 256>>>(qbase, krel + (size_t)r * NPC,
                                                  srcs[r], dsts[r],
                                                  p_rel + (size_t)(l * 3 + r) * NH,
                                                  alpha, amax, E[r]);
            edge_exp<<<(nt + 255) / 256, 256>>>(dsts[r], amax, alpha, den, E[r]);
            int nt2 = E[r] * 32;
            edge_scatter<<<(nt2 + 255) / 256, 256>>>(vrel + (size_t)r * NPC,
                                                     srcs[r], dsts[r], alpha, den,
                                                     agg + (dt ? NPC : 0), E[r]);
        }

        for (int t = 0; t < 2; t++) {
            int Mt = t ? NA : NP;
            size_t off = t ? (size_t)NPC : 0;
            float* outp = (l == 1) ? ((float*)d_out + off) : (xb[1 - cur] + off);
            TileArgs ta{};
            ta.wp[0] = slot(8 + t);
            ta.bias[0] = a_b + (l * 2 + t) * CDIM;
            ta.out[0] = outp;
            run_gemm(agg + off, ta, 1, Mt, 1, 2, xb[cur] + off, skip + l * 2 + t);
        }
        cur = 1 - cur;
    }
}

// round 4
// speedup vs baseline: 2.0687x; 1.7563x over previous
#include <cuda_runtime.h>
#include <cuda_bf16.h>
#include <math.h>
#include <stdint.h>

#define NP 100000
#define NA 50000
#define CDIM 128
#define CC (CDIM*CDIM)
#define NH 4
#define NPC (NP*CDIM)
#define EMAX 300000

#define PITCH 136                 // bf16 per row in staged images
#define PITCHB 272                // bytes
#define IMG_B16 (128*PITCH)       // 17408 bf16 per image
#define IMG_BYTES (IMG_B16*2)     // 34816 bytes
#define SLOT_U32 (IMG_B16)        // hi+lo images = 17408 u32 per slot

// ---------------- scratch (device globals) -----------------------------------
__device__ float g_x[2][(NP+NA)*CDIM];
__device__ float g_q[(NP+NA)*CDIM];
__device__ float g_krel[3][NPC];
__device__ float g_vrel[3][NPC];
__device__ float g_agg[(NP+NA)*CDIM];
__device__ float g_Wk[3][CC];
__device__ float g_Wv[3][CC];
__device__ float g_bk[3][CDIM];
__device__ float g_bv[3][CDIM];
__device__ uint32_t g_wpack[10][SLOT_U32];
__device__ int g_rowptr[3][NP+1];
__device__ int g_csrc[3][EMAX];
__device__ int g_cnt[NP];
__device__ int g_bsum[64];

// ---------------- small helpers ----------------------------------------------
__device__ __forceinline__ float gelu_f(float x) {
    return 0.5f * x * (1.0f + erff(x * 0.7071067811865476f));
}
__global__ void fill_i(int* __restrict__ p, int v, int n) {
    int i = blockIdx.x * blockDim.x + threadIdx.x;
    if (i < n) p[i] = v;
}
__global__ void copy_i(const int* __restrict__ a, int* __restrict__ b, int n) {
    int i = blockIdx.x * blockDim.x + threadIdx.x;
    if (i < n) b[i] = a[i];
}
__global__ void hist_k(const int* __restrict__ dst, int* __restrict__ cnt, int E) {
    int i = blockIdx.x * blockDim.x + threadIdx.x;
    if (i < E) atomicAdd(&cnt[dst[i]], 1);
}
// scan1: 256 threads x 16 elems = 4096/block; writes inclusive prefix to rp1[idx] (= rowptr[idx+1])
__global__ void scan1(const int* __restrict__ cnt, int* __restrict__ rp1,
                      int* __restrict__ bsum, int n) {
    __shared__ int sm[256];
    int base = blockIdx.x * 4096;
    int idx0 = base + threadIdx.x * 16;
    int v[16]; int t = 0;
#pragma unroll
    for (int j = 0; j < 16; j++) { int ix = idx0 + j; v[j] = (ix < n) ? cnt[ix] : 0; t += v[j]; }
    sm[threadIdx.x] = t;
    __syncthreads();
    for (int off = 1; off < 256; off <<= 1) {
        int x = 0;
        if ((int)threadIdx.x >= off) x = sm[threadIdx.x - off];
        __syncthreads();
        if ((int)threadIdx.x >= off) sm[threadIdx.x] += x;
        __syncthreads();
    }
    int run = sm[threadIdx.x] - t;
#pragma unroll
    for (int j = 0; j < 16; j++) { run += v[j]; int ix = idx0 + j; if (ix < n) rp1[ix] = run; }
    if (threadIdx.x == 255) bsum[blockIdx.x] = sm[255];
}
__global__ void scan2(int* __restrict__ bsum, int nb) {
    int tid = threadIdx.x;
    int orig = (tid < nb) ? bsum[tid] : 0;
    int v = orig;
    for (int off = 1; off < 32; off <<= 1) {
        int x = __shfl_up_sync(0xffffffffu, v, off);
        if (tid >= off) v += x;
    }
    if (tid < nb) bsum[tid] = v - orig;
}
__global__ void scan3(int* __restrict__ rowptr, const int* __restrict__ bsum, int n) {
    int i = blockIdx.x * blockDim.x + threadIdx.x;
    if (i < n) rowptr[i + 1] += bsum[i >> 12];
    if (i == 0) rowptr[0] = 0;
}
__global__ void csr_fill(const int* __restrict__ src, const int* __restrict__ dst,
                         int* __restrict__ cursor, int* __restrict__ csrc, int E) {
    int i = blockIdx.x * blockDim.x + threadIdx.x;
    if (i >= E) return;
    int pos = atomicAdd(&cursor[dst[i]], 1);
    csrc[pos] = src[i];
}

// ---------------- PTX helpers -------------------------------------------------
__device__ __forceinline__ uint32_t smem_u32(const void* p) {
    uint32_t a;
    asm("{ .reg .u64 t; cvta.to.shared.u64 t, %1; cvt.u32.u64 %0, t; }" : "=r"(a) : "l"(p));
    return a;
}
__device__ __forceinline__ uint32_t pk_bf2(__nv_bfloat16 a, __nv_bfloat16 b) {
    __nv_bfloat162 t = __halves2bfloat162(a, b);
    return *reinterpret_cast<uint32_t*>(&t);
}
__device__ __forceinline__ void ldsm4(uint32_t* r, uint32_t addr) {
    asm volatile("ldmatrix.sync.aligned.m8n8.x4.shared.b16 {%0,%1,%2,%3}, [%4];"
        : "=r"(r[0]), "=r"(r[1]), "=r"(r[2]), "=r"(r[3]) : "r"(addr));
}
__device__ __forceinline__ void mma16816(float* c, const uint32_t* a, const uint32_t* b) {
    asm volatile("mma.sync.aligned.m16n8k16.row.col.f32.bf16.bf16.f32 "
        "{%0,%1,%2,%3}, {%4,%5,%6,%7}, {%8,%9}, {%0,%1,%2,%3};"
        : "+f"(c[0]), "+f"(c[1]), "+f"(c[2]), "+f"(c[3])
        : "r"(a[0]), "r"(a[1]), "r"(a[2]), "r"(a[3]), "r"(b[0]), "r"(b[1]));
}
__device__ __forceinline__ void cp16(uint32_t dst, const void* src) {
    asm volatile("cp.async.cg.shared.global [%0], [%1], 16;" :: "r"(dst), "l"(src));
}

// ---------------- weight packing ----------------------------------------------
struct PackSrc { const float* w[10]; int count; };
__global__ void pack_weights(PackSrc ps, uint32_t* dstbase) {
    int m = blockIdx.x;
    if (m >= ps.count) return;
    const float* W = ps.w[m];
    uint32_t* hi = dstbase + (size_t)m * SLOT_U32;
    uint32_t* lo = hi + IMG_B16 / 2;
    int n = threadIdx.x;
    int k0 = blockIdx.y * 16;
    for (int k = k0; k < k0 + 16; k += 2) {
        float a0 = W[k * 128 + n], a1 = W[(k + 1) * 128 + n];
        __nv_bfloat16 h0 = __float2bfloat16(a0), h1 = __float2bfloat16(a1);
        float r0 = a0 - __bfloat162float(h0), r1 = a1 - __bfloat162float(h1);
        int idx = n * (PITCH / 2) + (k >> 1);
        hi[idx] = pk_bf2(h0, h1);
        lo[idx] = pk_bf2(__float2bfloat16(r0), __float2bfloat16(r1));
    }
}

// ---------------- composite relation weights ----------------------------------
__global__ void build_comp(const float* __restrict__ kw, const float* __restrict__ kb,
                           const float* __restrict__ vw, const float* __restrict__ vb,
                           const float* __restrict__ arel, const float* __restrict__ mrel,
                           float* __restrict__ Wk, float* __restrict__ bk,
                           float* __restrict__ Wv, float* __restrict__ bv) {
    int c = blockIdx.x, r = blockIdx.y, j = threadIdx.x;
    int st = (r == 1) ? 1 : 0;
    int h = j >> 5, e = j & 31;
    const float* kwp = kw + ((size_t)st * CDIM + c) * CDIM + h * 32;
    const float* vwp = vw + ((size_t)st * CDIM + c) * CDIM + h * 32;
    const float* ap  = arel + (size_t)(r * NH + h) * 1024 + e;
    const float* mp  = mrel + (size_t)(r * NH + h) * 1024 + e;
    float sk = 0.f, sv = 0.f;
#pragma unroll
    for (int d = 0; d < 32; d++) {
        sk += kwp[d] * ap[d * 32];
        sv += vwp[d] * mp[d * 32];
    }
    Wk[(size_t)r * CC + (size_t)c * CDIM + j] = sk;
    Wv[(size_t)r * CC + (size_t)c * CDIM + j] = sv;
    if (c == 0) {
        float bks = 0.f, bvs = 0.f;
        const float* kbp = kb + st * CDIM + h * 32;
        const float* vbp = vb + st * CDIM + h * 32;
#pragma unroll
        for (int d = 0; d < 32; d++) {
            bks += kbp[d] * ap[d * 32];
            bvs += vbp[d] * mp[d * 32];
        }
        bk[r * CDIM + j] = bks;
        bv[r * CDIM + j] = bvs;
    }
}

// ---------------- tensor-core GEMM (512 thr, cp.async double-buffered B) ------
struct TileArgs {
    const uint4* wp[5];
    const float* bias[5];
    float*       out[5];
};

#define SM_A_HI  0
#define SM_A_LO  IMG_BYTES
#define SM_B(b)  (2*IMG_BYTES + (b)*2*IMG_BYTES)
#define SM_NEED  (6*IMG_BYTES)          // 208896 bytes

__device__ __forceinline__ void prefetch_B(uint32_t dstb, const uint4* src, int tid) {
#pragma unroll
    for (int i = 0; i < 8; i++) cp16(dstb + (uint32_t)(i * 512 + tid) * 16, src + i * 512 + tid);
    if (tid < 256) cp16(dstb + (uint32_t)(4096 + tid) * 16, src + 4096 + tid);
    asm volatile("cp.async.commit_group;" ::: "memory");
}

__global__ void __launch_bounds__(512, 1)
gemm_mma(const float* __restrict__ A, TileArgs ta, int ntiles, int M,
         int aop, int eop, const float* __restrict__ xold, const float* __restrict__ skipp) {
    extern __shared__ char sm[];
    uint32_t sb = smem_u32(sm);
    int tid = threadIdx.x, lane = tid & 31, wid = tid >> 5;
    int wm = wid & 3, wn = wid >> 2;           // 4 m-warps x 4 n-warps (32x32 per warp)
    int rowBase = blockIdx.x * 128;

    // prefetch first B tile
    prefetch_B(sb + SM_B(0), ta.wp[0], tid);

    // ---- stage A: fp32 -> gelu? -> bf16 hi/lo, pitched ----
#pragma unroll 4
    for (int it = 0; it < 8; it++) {
        int f = it * 512 + tid;
        int m = f >> 5, k = (f & 31) << 2;
        int row = rowBase + m;
        float4 v = make_float4(0.f, 0.f, 0.f, 0.f);
        if (row < M) v = *(const float4*)(A + (size_t)row * CDIM + k);
        if (aop) { v.x = gelu_f(v.x); v.y = gelu_f(v.y); v.z = gelu_f(v.z); v.w = gelu_f(v.w); }
        __nv_bfloat16 h0 = __float2bfloat16(v.x), h1 = __float2bfloat16(v.y);
        __nv_bfloat16 h2 = __float2bfloat16(v.z), h3 = __float2bfloat16(v.w);
        float r0 = v.x - __bfloat162float(h0), r1 = v.y - __bfloat162float(h1);
        float r2 = v.z - __bfloat162float(h2), r3 = v.w - __bfloat162float(h3);
        uint32_t off = (uint32_t)(m * PITCHB + k * 2);
        *(uint2*)(sm + SM_A_HI + off) = make_uint2(pk_bf2(h0, h1), pk_bf2(h2, h3));
        *(uint2*)(sm + SM_A_LO + off) = make_uint2(
            pk_bf2(__float2bfloat16(r0), __float2bfloat16(r1)),
            pk_bf2(__float2bfloat16(r2), __float2bfloat16(r3)));
    }

    // ldmatrix bases
    int aRow = wm * 32 + (lane & 15);
    uint32_t aKoff = (lane & 16) ? 16u : 0u;
    uint32_t aBaseHi = sb + SM_A_HI + aRow * PITCHB + aKoff;
    uint32_t aBaseLo = aBaseHi + IMG_BYTES;
    int bN = wn * 32 + (lane & 7) + ((lane & 16) ? 8 : 0);
    uint32_t bKoff = (lane & 8) ? 16u : 0u;
    uint32_t bOff = bN * PITCHB + bKoff;

    float skv = 0.f;
    if (eop == 2) skv = 1.f / (1.f + expf(-*skipp));
    int g = lane >> 2, tg = lane & 3;

    for (int b = 0; b < ntiles; b++) {
        if (b + 1 < ntiles) {
            prefetch_B(sb + SM_B((b + 1) & 1), ta.wp[b + 1], tid);
            asm volatile("cp.async.wait_group 1;" ::: "memory");
        } else {
            asm volatile("cp.async.wait_group 0;" ::: "memory");
        }
        __syncthreads();

        float acc[2][4][4];
#pragma unroll
        for (int i = 0; i < 2; i++)
#pragma unroll
            for (int j = 0; j < 4; j++)
#pragma unroll
                for (int q = 0; q < 4; q++) acc[i][j][q] = 0.f;

        uint32_t bHi0 = sb + SM_B(b & 1) + bOff;
        uint32_t aHi = aBaseHi, aLo = aBaseLo, bHi = bHi0, bLo = bHi0 + IMG_BYTES;
#pragma unroll
        for (int ks = 0; ks < 8; ks++) {
            uint32_t ah[2][4], al[2][4], bh[2][4], bl[2][4];
            ldsm4(ah[0], aHi); ldsm4(ah[1], aHi + 16 * PITCHB);
            ldsm4(al[0], aLo); ldsm4(al[1], aLo + 16 * PITCHB);
            ldsm4(bh[0], bHi); ldsm4(bh[1], bHi + 16 * PITCHB);
            ldsm4(bl[0], bLo); ldsm4(bl[1], bLo + 16 * PITCHB);
#pragma unroll
            for (int i = 0; i < 2; i++)
#pragma unroll
                for (int j = 0; j < 4; j++) {
                    const uint32_t* bph = &bh[j >> 1][(j & 1) * 2];
                    mma16816(acc[i][j], ah[i], bph);
                    mma16816(acc[i][j], al[i], bph);
                    mma16816(acc[i][j], ah[i], &bl[j >> 1][(j & 1) * 2]);
                }
            aHi += 32; aLo += 32; bHi += 32; bLo += 32;
        }
        __syncthreads();   // ldmatrix reads done before next prefetch overwrites

        // ---- epilogue ----
        const float* bias = ta.bias[b];
        float* out = ta.out[b];
#pragma unroll
        for (int i = 0; i < 2; i++) {
            int r0 = rowBase + wm * 32 + i * 16 + g;
#pragma unroll
            for (int j = 0; j < 4; j++) {
                int col = wn * 32 + j * 8 + tg * 2;
                float b0 = bias[col], b1 = bias[col + 1];
#pragma unroll
                for (int half = 0; half < 2; half++) {
                    int row = r0 + half * 8;
                    if (row >= M) continue;
                    float v0 = acc[i][j][half * 2 + 0] + b0;
                    float v1 = acc[i][j][half * 2 + 1] + b1;
                    if (eop == 1) {
                        v0 = fmaxf(v0, 0.f); v1 = fmaxf(v1, 0.f);
                    } else if (eop == 2) {
                        float2 xo = *(const float2*)(xold + (size_t)row * CDIM + col);
                        v0 = skv * v0 + (1.f - skv) * xo.x;
                        v1 = skv * v1 + (1.f - skv) * xo.y;
                    }
                    *(float2*)(out + (size_t)row * CDIM + col) = make_float2(v0, v1);
                }
            }
        }
    }
}

// ---------------- edge phase: CSR gather + online softmax ----------------------
// one warp per destination node; up to 2 relation types fused
__global__ void __launch_bounds__(256)
edge_gather(const float* __restrict__ q, float* __restrict__ agg, int N, int nrel,
            const float* __restrict__ kr0, const float* __restrict__ vr0,
            const int* __restrict__ rp0, const int* __restrict__ cs0,
            const float* __restrict__ pr0,
            const float* __restrict__ kr1, const float* __restrict__ vr1,
            const int* __restrict__ rp1, const int* __restrict__ cs1,
            const float* __restrict__ pr1) {
    int w = (blockIdx.x * blockDim.x + threadIdx.x) >> 5;
    if (w >= N) return;
    int lane = threadIdx.x & 31;
    int h = lane >> 3;
    float4 qv = *(const float4*)(q + (size_t)w * CDIM + lane * 4);
    float4 tot = make_float4(0.f, 0.f, 0.f, 0.f);
    for (int rel = 0; rel < nrel; rel++) {
        const float* kr = rel ? kr1 : kr0;
        const float* vr = rel ? vr1 : vr0;
        const int* rp = rel ? rp1 : rp0;
        const int* cs = rel ? cs1 : cs0;
        const float* prl = rel ? pr1 : pr0;
        float pscale = prl[h] * 0.17677669529663687f;
        int beg = rp[w], end = rp[w + 1];
        float m = -INFINITY, s = 0.f;
        float4 acc = make_float4(0.f, 0.f, 0.f, 0.f);
        for (int e = beg; e < end; e++) {
            int sidx = cs[e];
            float4 kv = *(const float4*)(kr + (size_t)sidx * CDIM + lane * 4);
            float dot = qv.x * kv.x + qv.y * kv.y + qv.z * kv.z + qv.w * kv.w;
            dot += __shfl_xor_sync(0xffffffffu, dot, 1);
            dot += __shfl_xor_sync(0xffffffffu, dot, 2);
            dot += __shfl_xor_sync(0xffffffffu, dot, 4);
            float alpha = dot * pscale;
            float mn = fmaxf(m, alpha);
            float sc = __expf(m - mn);
            float p = __expf(alpha - mn);
            s = s * sc + p;
            float4 vv = *(const float4*)(vr + (size_t)sidx * CDIM + lane * 4);
            acc.x = acc.x * sc + p * vv.x;
            acc.y = acc.y * sc + p * vv.y;
            acc.z = acc.z * sc + p * vv.z;
            acc.w = acc.w * sc + p * vv.w;
            m = mn;
        }
        float inv = 1.f / (s + 1e-16f);
        tot.x += acc.x * inv; tot.y += acc.y * inv;
        tot.z += acc.z * inv; tot.w += acc.w * inv;
    }
    *(float4*)(agg + (size_t)w * CDIM + lane * 4) = tot;
}

// ---------------- host orchestration -------------------------------------------
extern "C" void kernel_launch(void* const* d_in, const int* in_sizes, int n_in,
                              void* d_out, int out_size) {
    const float* x_paper  = (const float*)d_in[0];
    const float* x_author = (const float*)d_in[1];
    const float* lin_w = (const float*)d_in[2];
    const float* lin_b = (const float*)d_in[3];
    const float* k_w = (const float*)d_in[4];
    const float* k_b = (const float*)d_in[5];
    const float* q_w = (const float*)d_in[6];
    const float* q_b = (const float*)d_in[7];
    const float* v_w = (const float*)d_in[8];
    const float* v_b = (const float*)d_in[9];
    const float* a_w = (const float*)d_in[10];
    const float* a_b = (const float*)d_in[11];
    const float* skip  = (const float*)d_in[12];
    const float* a_rel = (const float*)d_in[13];
    const float* m_rel = (const float*)d_in[14];
    const float* p_rel = (const float*)d_in[15];
    const int* srcs[3] = {(const int*)d_in[16], (const int*)d_in[18], (const int*)d_in[20]};
    const int* dsts[3] = {(const int*)d_in[17], (const int*)d_in[19], (const int*)d_in[21]};
    int E[3] = {in_sizes[16], in_sizes[18], in_sizes[20]};

    cudaFuncSetAttribute(gemm_mma, cudaFuncAttributeMaxDynamicSharedMemorySize, SM_NEED);

    void* p;
    float *xb[2], *qb, *krel, *vrel, *agg, *Wk, *Wv, *bk, *bv;
    uint32_t* wpack;
    int *rowptr[3], *csrc[3], *cnt, *bsum;
    cudaGetSymbolAddress(&p, g_x);    xb[0] = (float*)p; xb[1] = xb[0] + (size_t)(NP + NA) * CDIM;
    cudaGetSymbolAddress(&p, g_q);    qb    = (float*)p;
    cudaGetSymbolAddress(&p, g_krel); krel  = (float*)p;
    cudaGetSymbolAddress(&p, g_vrel); vrel  = (float*)p;
    cudaGetSymbolAddress(&p, g_agg);  agg   = (float*)p;
    cudaGetSymbolAddress(&p, g_Wk);   Wk    = (float*)p;
    cudaGetSymbolAddress(&p, g_Wv);   Wv    = (float*)p;
    cudaGetSymbolAddress(&p, g_bk);   bk    = (float*)p;
    cudaGetSymbolAddress(&p, g_bv);   bv    = (float*)p;
    cudaGetSymbolAddress(&p, g_wpack);wpack = (uint32_t*)p;
    cudaGetSymbolAddress(&p, g_rowptr);
    for (int r = 0; r < 3; r++) rowptr[r] = (int*)p + (size_t)r * (NP + 1);
    cudaGetSymbolAddress(&p, g_csrc);
    for (int r = 0; r < 3; r++) csrc[r] = (int*)p + (size_t)r * EMAX;
    cudaGetSymbolAddress(&p, g_cnt);  cnt  = (int*)p;
    cudaGetSymbolAddress(&p, g_bsum); bsum = (int*)p;

    auto slot = [&](int s) { return (const uint4*)(wpack + (size_t)s * SLOT_U32); };
    auto run_gemm = [&](const float* A, TileArgs& ta, int nt, int M, int aop, int eop,
                        const float* xold, const float* sp) {
        gemm_mma<<<(M + 127) / 128, 512, SM_NEED>>>(A, ta, nt, M, aop, eop, xold, sp);
    };

    // ---- CSR build (once; edges shared across layers) ----
    for (int r = 0; r < 3; r++) {
        int Nd = (r == 2) ? NA : NP;
        fill_i<<<(Nd + 255) / 256, 256>>>(cnt, 0, Nd);
        hist_k<<<(E[r] + 255) / 256, 256>>>(dsts[r], cnt, E[r]);
        int nb = (Nd + 4095) / 4096;
        scan1<<<nb, 256>>>(cnt, rowptr[r] + 1, bsum, Nd);
        scan2<<<1, 32>>>(bsum, nb);
        scan3<<<(Nd + 255) / 256, 256>>>(rowptr[r], bsum, Nd);
        copy_i<<<(Nd + 255) / 256, 256>>>(rowptr[r], cnt, Nd);
        csr_fill<<<(E[r] + 255) / 256, 256>>>(srcs[r], dsts[r], cnt, csrc[r], E[r]);
    }

    // ---- wrapper: per-type linear + relu ----
    {
        PackSrc ps{};
        ps.w[0] = lin_w; ps.w[1] = lin_w + CC; ps.count = 2;
        pack_weights<<<dim3(2, 8), 128>>>(ps, wpack);
        TileArgs ta{};
        ta.wp[0] = slot(0); ta.bias[0] = lin_b; ta.out[0] = xb[0];
        run_gemm(x_paper, ta, 1, NP, 0, 1, nullptr, nullptr);
        ta.wp[0] = slot(1); ta.bias[0] = lin_b + CDIM; ta.out[0] = xb[0] + NPC;
        run_gemm(x_author, ta, 1, NA, 0, 1, nullptr, nullptr);
    }

    int cur = 0;
    for (int l = 0; l < 2; l++) {
        build_comp<<<dim3(CDIM, 3), CDIM>>>(
            k_w + (size_t)l * 2 * CC, k_b + l * 2 * CDIM,
            v_w + (size_t)l * 2 * CC, v_b + l * 2 * CDIM,
            a_rel + (size_t)l * 3 * NH * 1024, m_rel + (size_t)l * 3 * NH * 1024,
            Wk, bk, Wv, bv);

        // slots: 0:q_p 1:q_a 2:Wk0 3:Wv0 4:Wk2 5:Wv2 6:Wk1 7:Wv1 8:aw_p 9:aw_a
        {
            PackSrc ps{};
            ps.w[0] = q_w + (size_t)(l * 2 + 0) * CC;
            ps.w[1] = q_w + (size_t)(l * 2 + 1) * CC;
            ps.w[2] = Wk;          ps.w[3] = Wv;
            ps.w[4] = Wk + 2 * CC; ps.w[5] = Wv + 2 * CC;
            ps.w[6] = Wk + CC;     ps.w[7] = Wv + CC;
            ps.w[8] = a_w + (size_t)(l * 2 + 0) * CC;
            ps.w[9] = a_w + (size_t)(l * 2 + 1) * CC;
            ps.count = 10;
            pack_weights<<<dim3(10, 8), 128>>>(ps, wpack);
        }

        // fused GEMM over paper source: q_p | krel0 | vrel0 | krel2 | vrel2
        {
            TileArgs ta{};
            ta.wp[0] = slot(0); ta.bias[0] = q_b + (l * 2 + 0) * CDIM; ta.out[0] = qb;
            ta.wp[1] = slot(2); ta.bias[1] = bk;             ta.out[1] = krel;
            ta.wp[2] = slot(3); ta.bias[2] = bv;             ta.out[2] = vrel;
            ta.wp[3] = slot(4); ta.bias[3] = bk + 2 * CDIM;  ta.out[3] = krel + 2 * (size_t)NPC;
            ta.wp[4] = slot(5); ta.bias[4] = bv + 2 * CDIM;  ta.out[4] = vrel + 2 * (size_t)NPC;
            run_gemm(xb[cur], ta, 5, NP, 0, 0, nullptr, nullptr);
        }
        // fused GEMM over author source: q_a | krel1 | vrel1
        {
            TileArgs ta{};
            ta.wp[0] = slot(1); ta.bias[0] = q_b + (l * 2 + 1) * CDIM; ta.out[0] = qb + NPC;
            ta.wp[1] = slot(6); ta.bias[1] = bk + CDIM;      ta.out[1] = krel + (size_t)NPC;
            ta.wp[2] = slot(7); ta.bias[2] = bv + CDIM;      ta.out[2] = vrel + (size_t)NPC;
            run_gemm(xb[cur] + NPC, ta, 3, NA, 0, 0, nullptr, nullptr);
        }

        // edge phase: gather per destination node (zero atomics, writes agg)
        edge_gather<<<(NP * 32 + 255) / 256, 256>>>(
            qb, agg, NP, 2,
            krel, vrel, rowptr[0], csrc[0], p_rel + (size_t)(l * 3 + 0) * NH,
            krel + (size_t)NPC, vrel + (size_t)NPC, rowptr[1], csrc[1],
            p_rel + (size_t)(l * 3 + 1) * NH);
        edge_gather<<<(NA * 32 + 255) / 256, 256>>>(
            qb + NPC, agg + NPC, NA, 1,
            krel + 2 * (size_t)NPC, vrel + 2 * (size_t)NPC, rowptr[2], csrc[2],
            p_rel + (size_t)(l * 3 + 2) * NH,
            nullptr, nullptr, nullptr, nullptr, nullptr);

        // output projection: gelu(agg) @ a_w + bias, skip-blend
        for (int t = 0; t < 2; t++) {
            int Mt = t ? NA : NP;
            size_t off = t ? (size_t)NPC : 0;
            float* outp = (l == 1) ? ((float*)d_out + off) : (xb[1 - cur] + off);
            TileArgs ta{};
            ta.wp[0] = slot(8 + t);
            ta.bias[0] = a_b + (l * 2 + t) * CDIM;
            ta.out[0] = outp;
            run_gemm(agg + off, ta, 1, Mt, 1, 2, xb[cur] + off, skip + l * 2 + t);
        }
        cur = 1 - cur;
    }
}

// round 6
// speedup vs baseline: 2.2881x; 1.1061x over previous
#include <cuda_runtime.h>
#include <cuda_bf16.h>
#include <math.h>
#include <stdint.h>

#define NP 100000
#define NA 50000
#define CDIM 128
#define CC (CDIM*CDIM)
#define NH 4
#define NPC (NP*CDIM)
#define EMAX 300000

#define PITCH 136                 // bf16 per row in staged images
#define PITCHB 272                // bytes
#define IMG_B16 (128*PITCH)       // 17408 bf16 per image
#define IMG_BYTES (IMG_B16*2)     // 34816 bytes
#define SLOT_U32 (IMG_B16)        // hi+lo images = 17408 u32 per slot
#define NSLOT 12                  // 0-9: per-layer, 10-11: wrapper (never overwritten)

// ---------------- scratch (device globals) -----------------------------------
__device__ float g_x[2][(NP+NA)*CDIM];
__device__ float g_q[(NP+NA)*CDIM];
__device__ float g_krel[3][NPC];
__device__ float g_vrel[3][NPC];
__device__ float g_agg[(NP+NA)*CDIM];
__device__ float g_Wk[3][CC];
__device__ float g_Wv[3][CC];
__device__ float g_bk[3][CDIM];
__device__ float g_bv[3][CDIM];
__device__ uint32_t g_wpack[NSLOT][SLOT_U32];
__device__ int g_rowptr[3][NP+1];
__device__ int g_csrc[3][EMAX];
__device__ int g_cnt[NP];
__device__ int g_bsum[64];

// ---------------- small helpers ----------------------------------------------
__device__ __forceinline__ float gelu_f(float x) {
    return 0.5f * x * (1.0f + erff(x * 0.7071067811865476f));
}
__global__ void fill_i(int* __restrict__ p, int v, int n) {
    int i = blockIdx.x * blockDim.x + threadIdx.x;
    if (i < n) p[i] = v;
}
__global__ void hist_k(const int* __restrict__ dst, int* __restrict__ cnt, int E) {
    int i = blockIdx.x * blockDim.x + threadIdx.x;
    if (i < E) atomicAdd(&cnt[dst[i]], 1);
}
// scan1: 256 threads x 16 elems = 4096/block; inclusive prefix to rp1[idx] (= rowptr[idx+1])
__global__ void scan1(const int* __restrict__ cnt, int* __restrict__ rp1,
                      int* __restrict__ bsum, int n) {
    __shared__ int sm[256];
    int base = blockIdx.x * 4096;
    int idx0 = base + threadIdx.x * 16;
    int v[16]; int t = 0;
#pragma unroll
    for (int j = 0; j < 16; j++) { int ix = idx0 + j; v[j] = (ix < n) ? cnt[ix] : 0; t += v[j]; }
    sm[threadIdx.x] = t;
    __syncthreads();
    for (int off = 1; off < 256; off <<= 1) {
        int x = 0;
        if ((int)threadIdx.x >= off) x = sm[threadIdx.x - off];
        __syncthreads();
        if ((int)threadIdx.x >= off) sm[threadIdx.x] += x;
        __syncthreads();
    }
    int run = sm[threadIdx.x] - t;
#pragma unroll
    for (int j = 0; j < 16; j++) { run += v[j]; int ix = idx0 + j; if (ix < n) rp1[ix] = run; }
    if (threadIdx.x == 255) bsum[blockIdx.x] = sm[255];
}
__global__ void scan2(int* __restrict__ bsum, int nb) {
    int tid = threadIdx.x;
    int orig = (tid < nb) ? bsum[tid] : 0;
    int v = orig;
    for (int off = 1; off < 32; off <<= 1) {
        int x = __shfl_up_sync(0xffffffffu, v, off);
        if (tid >= off) v += x;
    }
    if (tid < nb) bsum[tid] = v - orig;
}
// scan3: finalize rowptr AND write cursor (= final rowptr value per node)
__global__ void scan3(int* __restrict__ rowptr, const int* __restrict__ bsum,
                      int* __restrict__ cursor, int n) {
    int i = blockIdx.x * blockDim.x + threadIdx.x;
    if (i < n) {
        int val = rowptr[i + 1] + bsum[i >> 12];
        rowptr[i + 1] = val;
        if (i + 1 < n) cursor[i + 1] = val;
    }
    if (i == 0) { rowptr[0] = 0; cursor[0] = 0; }
}
__global__ void csr_fill(const int* __restrict__ src, const int* __restrict__ dst,
                         int* __restrict__ cursor, int* __restrict__ csrc, int E) {
    int i = blockIdx.x * blockDim.x + threadIdx.x;
    if (i >= E) return;
    int pos = atomicAdd(&cursor[dst[i]], 1);
    csrc[pos] = src[i];
}

// ---------------- PTX helpers -------------------------------------------------
__device__ __forceinline__ uint32_t smem_u32(const void* p) {
    uint32_t a;
    asm("{ .reg .u64 t; cvta.to.shared.u64 t, %1; cvt.u32.u64 %0, t; }" : "=r"(a) : "l"(p));
    return a;
}
__device__ __forceinline__ uint32_t pk_bf2(__nv_bfloat16 a, __nv_bfloat16 b) {
    __nv_bfloat162 t = __halves2bfloat162(a, b);
    return *reinterpret_cast<uint32_t*>(&t);
}
__device__ __forceinline__ void ldsm4(uint32_t* r, uint32_t addr) {
    asm volatile("ldmatrix.sync.aligned.m8n8.x4.shared.b16 {%0,%1,%2,%3}, [%4];"
        : "=r"(r[0]), "=r"(r[1]), "=r"(r[2]), "=r"(r[3]) : "r"(addr));
}
__device__ __forceinline__ void mma16816(float* c, const uint32_t* a, const uint32_t* b) {
    asm volatile("mma.sync.aligned.m16n8k16.row.col.f32.bf16.bf16.f32 "
        "{%0,%1,%2,%3}, {%4,%5,%6,%7}, {%8,%9}, {%0,%1,%2,%3};"
        : "+f"(c[0]), "+f"(c[1]), "+f"(c[2]), "+f"(c[3])
        : "r"(a[0]), "r"(a[1]), "r"(a[2]), "r"(a[3]), "r"(b[0]), "r"(b[1]));
}
__device__ __forceinline__ void cp16(uint32_t dst, const void* src) {
    asm volatile("cp.async.cg.shared.global [%0], [%1], 16;" :: "r"(dst), "l"(src));
}

// ---------------- weight packing ----------------------------------------------
struct PackSrc { const float* w[10]; int count; int slot0; };
__global__ void pack_weights(PackSrc ps, uint32_t* dstbase) {
    int m = blockIdx.x;
    if (m >= ps.count) return;
    const float* W = ps.w[m];
    uint32_t* hi = dstbase + (size_t)(ps.slot0 + m) * SLOT_U32;
    uint32_t* lo = hi + IMG_B16 / 2;
    int n = threadIdx.x;
    int k0 = blockIdx.y * 16;
    for (int k = k0; k < k0 + 16; k += 2) {
        float a0 = W[k * 128 + n], a1 = W[(k + 1) * 128 + n];
        __nv_bfloat16 h0 = __float2bfloat16(a0), h1 = __float2bfloat16(a1);
        float r0 = a0 - __bfloat162float(h0), r1 = a1 - __bfloat162float(h1);
        int idx = n * (PITCH / 2) + (k >> 1);
        hi[idx] = pk_bf2(h0, h1);
        lo[idx] = pk_bf2(__float2bfloat16(r0), __float2bfloat16(r1));
    }
}

// ---------------- composite relation weights ----------------------------------
__global__ void build_comp(const float* __restrict__ kw, const float* __restrict__ kb,
                           const float* __restrict__ vw, const float* __restrict__ vb,
                           const float* __restrict__ arel, const float* __restrict__ mrel,
                           float* __restrict__ Wk, float* __restrict__ bk,
                           float* __restrict__ Wv, float* __restrict__ bv) {
    int c = blockIdx.x, r = blockIdx.y, j = threadIdx.x;
    int st = (r == 1) ? 1 : 0;
    int h = j >> 5, e = j & 31;
    const float* kwp = kw + ((size_t)st * CDIM + c) * CDIM + h * 32;
    const float* vwp = vw + ((size_t)st * CDIM + c) * CDIM + h * 32;
    const float* ap  = arel + (size_t)(r * NH + h) * 1024 + e;
    const float* mp  = mrel + (size_t)(r * NH + h) * 1024 + e;
    float sk = 0.f, sv = 0.f;
#pragma unroll
    for (int d = 0; d < 32; d++) {
        sk += kwp[d] * ap[d * 32];
        sv += vwp[d] * mp[d * 32];
    }
    Wk[(size_t)r * CC + (size_t)c * CDIM + j] = sk;
    Wv[(size_t)r * CC + (size_t)c * CDIM + j] = sv;
    if (c == 0) {
        float bks = 0.f, bvs = 0.f;
        const float* kbp = kb + st * CDIM + h * 32;
        const float* vbp = vb + st * CDIM + h * 32;
#pragma unroll
        for (int d = 0; d < 32; d++) {
            bks += kbp[d] * ap[d * 32];
            bvs += vbp[d] * mp[d * 32];
        }
        bk[r * CDIM + j] = bks;
        bv[r * CDIM + j] = bvs;
    }
}

// ---------------- tensor-core GEMM (512 thr, cp.async double-buffered B) ------
struct TileArgs {
    const uint4* wp[5];
    const float* bias[5];
    float*       out[5];
};

#define SM_A_HI  0
#define SM_A_LO  IMG_BYTES
#define SM_B(b)  (2*IMG_BYTES + (b)*2*IMG_BYTES)
#define SM_NEED  (6*IMG_BYTES)          // 208896 bytes

__device__ __forceinline__ void prefetch_B(uint32_t dstb, const uint4* src, int tid) {
#pragma unroll
    for (int i = 0; i < 8; i++) cp16(dstb + (uint32_t)(i * 512 + tid) * 16, src + i * 512 + tid);
    if (tid < 256) cp16(dstb + (uint32_t)(4096 + tid) * 16, src + 4096 + tid);
    asm volatile("cp.async.commit_group;" ::: "memory");
}

__global__ void __launch_bounds__(512, 1)
gemm_mma(const float* __restrict__ A, TileArgs ta, int ntiles, int M,
         int aop, int eop, const float* __restrict__ xold, const float* __restrict__ skipp) {
    extern __shared__ char sm[];
    uint32_t sb = smem_u32(sm);
    int tid = threadIdx.x, lane = tid & 31, wid = tid >> 5;
    int wm = wid & 3, wn = wid >> 2;           // 4 m-warps x 4 n-warps (32x32 per warp)
    int rowBase = blockIdx.x * 128;

    prefetch_B(sb + SM_B(0), ta.wp[0], tid);

    // ---- stage A: fp32 -> gelu? -> bf16 hi/lo, pitched ----
#pragma unroll 4
    for (int it = 0; it < 8; it++) {
        int f = it * 512 + tid;
        int m = f >> 5, k = (f & 31) << 2;
        int row = rowBase + m;
        float4 v = make_float4(0.f, 0.f, 0.f, 0.f);
        if (row < M) v = *(const float4*)(A + (size_t)row * CDIM + k);
        if (aop) { v.x = gelu_f(v.x); v.y = gelu_f(v.y); v.z = gelu_f(v.z); v.w = gelu_f(v.w); }
        __nv_bfloat16 h0 = __float2bfloat16(v.x), h1 = __float2bfloat16(v.y);
        __nv_bfloat16 h2 = __float2bfloat16(v.z), h3 = __float2bfloat16(v.w);
        float r0 = v.x - __bfloat162float(h0), r1 = v.y - __bfloat162float(h1);
        float r2 = v.z - __bfloat162float(h2), r3 = v.w - __bfloat162float(h3);
        uint32_t off = (uint32_t)(m * PITCHB + k * 2);
        *(uint2*)(sm + SM_A_HI + off) = make_uint2(pk_bf2(h0, h1), pk_bf2(h2, h3));
        *(uint2*)(sm + SM_A_LO + off) = make_uint2(
            pk_bf2(__float2bfloat16(r0), __float2bfloat16(r1)),
            pk_bf2(__float2bfloat16(r2), __float2bfloat16(r3)));
    }

    int aRow = wm * 32 + (lane & 15);
    uint32_t aKoff = (lane & 16) ? 16u : 0u;
    uint32_t aBaseHi = sb + SM_A_HI + aRow * PITCHB + aKoff;
    uint32_t aBaseLo = aBaseHi + IMG_BYTES;
    int bN = wn * 32 + (lane & 7) + ((lane & 16) ? 8 : 0);
    uint32_t bKoff = (lane & 8) ? 16u : 0u;
    uint32_t bOff = bN * PITCHB + bKoff;

    float skv = 0.f;
    if (eop == 2) skv = 1.f / (1.f + expf(-*skipp));
    int g = lane >> 2, tg = lane & 3;

    for (int b = 0; b < ntiles; b++) {
        if (b + 1 < ntiles) {
            prefetch_B(sb + SM_B((b + 1) & 1), ta.wp[b + 1], tid);
            asm volatile("cp.async.wait_group 1;" ::: "memory");
        } else {
            asm volatile("cp.async.wait_group 0;" ::: "memory");
        }
        __syncthreads();

        float acc[2][4][4];
#pragma unroll
        for (int i = 0; i < 2; i++)
#pragma unroll
            for (int j = 0; j < 4; j++)
#pragma unroll
                for (int q = 0; q < 4; q++) acc[i][j][q] = 0.f;

        uint32_t bHi0 = sb + SM_B(b & 1) + bOff;
        uint32_t aHi = aBaseHi, aLo = aBaseLo, bHi = bHi0, bLo = bHi0 + IMG_BYTES;
#pragma unroll
        for (int ks = 0; ks < 8; ks++) {
            uint32_t ah[2][4], al[2][4], bh[2][4], bl[2][4];
            ldsm4(ah[0], aHi); ldsm4(ah[1], aHi + 16 * PITCHB);
            ldsm4(al[0], aLo); ldsm4(al[1], aLo + 16 * PITCHB);
            ldsm4(bh[0], bHi); ldsm4(bh[1], bHi + 16 * PITCHB);
            ldsm4(bl[0], bLo); ldsm4(bl[1], bLo + 16 * PITCHB);
#pragma unroll
            for (int i = 0; i < 2; i++)
#pragma unroll
                for (int j = 0; j < 4; j++) {
                    const uint32_t* bph = &bh[j >> 1][(j & 1) * 2];
                    mma16816(acc[i][j], ah[i], bph);
                    mma16816(acc[i][j], al[i], bph);
                    mma16816(acc[i][j], ah[i], &bl[j >> 1][(j & 1) * 2]);
                }
            aHi += 32; aLo += 32; bHi += 32; bLo += 32;
        }
        __syncthreads();

        const float* bias = ta.bias[b];
        float* out = ta.out[b];
#pragma unroll
        for (int i = 0; i < 2; i++) {
            int r0 = rowBase + wm * 32 + i * 16 + g;
#pragma unroll
            for (int j = 0; j < 4; j++) {
                int col = wn * 32 + j * 8 + tg * 2;
                float b0 = bias[col], b1 = bias[col + 1];
#pragma unroll
                for (int half = 0; half < 2; half++) {
                    int row = r0 + half * 8;
                    if (row >= M) continue;
                    float v0 = acc[i][j][half * 2 + 0] + b0;
                    float v1 = acc[i][j][half * 2 + 1] + b1;
                    if (eop == 1) {
                        v0 = fmaxf(v0, 0.f); v1 = fmaxf(v1, 0.f);
                    } else if (eop == 2) {
                        float2 xo = *(const float2*)(xold + (size_t)row * CDIM + col);
                        v0 = skv * v0 + (1.f - skv) * xo.x;
                        v1 = skv * v1 + (1.f - skv) * xo.y;
                    }
                    *(float2*)(out + (size_t)row * CDIM + col) = make_float2(v0, v1);
                }
            }
        }
    }
}

// ---------------- edge phase: CSR gather + online softmax (pipelined) ----------
__global__ void __launch_bounds__(256)
edge_gather(const float* __restrict__ q, float* __restrict__ agg, int N, int nrel,
            const float* __restrict__ kr0, const float* __restrict__ vr0,
            const int* __restrict__ rp0, const int* __restrict__ cs0,
            const float* __restrict__ pr0,
            const float* __restrict__ kr1, const float* __restrict__ vr1,
            const int* __restrict__ rp1, const int* __restrict__ cs1,
            const float* __restrict__ pr1) {
    int w = (blockIdx.x * blockDim.x + threadIdx.x) >> 5;
    if (w >= N) return;
    int lane = threadIdx.x & 31;
    int h = lane >> 3;
    float4 qv = *(const float4*)(q + (size_t)w * CDIM + lane * 4);
    float4 tot = make_float4(0.f, 0.f, 0.f, 0.f);
    for (int rel = 0; rel < nrel; rel++) {
        const float* kr = rel ? kr1 : kr0;
        const float* vr = rel ? vr1 : vr0;
        const int* rp = rel ? rp1 : rp0;
        const int* cs = rel ? cs1 : cs0;
        const float* prl = rel ? pr1 : pr0;
        float pscale = prl[h] * 0.17677669529663687f;
        int beg = rp[w], end = rp[w + 1];
        float m = -INFINITY, s = 0.f;
        float4 acc = make_float4(0.f, 0.f, 0.f, 0.f);
        float4 kv, vv;
        if (beg < end) {
            int sidx = cs[beg];
            kv = *(const float4*)(kr + (size_t)sidx * CDIM + lane * 4);
            vv = *(const float4*)(vr + (size_t)sidx * CDIM + lane * 4);
        }
        for (int e = beg; e < end; e++) {
            float4 kn, vn;
            if (e + 1 < end) {
                int sn = cs[e + 1];
                kn = *(const float4*)(kr + (size_t)sn * CDIM + lane * 4);
                vn = *(const float4*)(vr + (size_t)sn * CDIM + lane * 4);
            }
            float dot = qv.x * kv.x + qv.y * kv.y + qv.z * kv.z + qv.w * kv.w;
            dot += __shfl_xor_sync(0xffffffffu, dot, 1);
            dot += __shfl_xor_sync(0xffffffffu, dot, 2);
            dot += __shfl_xor_sync(0xffffffffu, dot, 4);
            float alpha = dot * pscale;
            float mn = fmaxf(m, alpha);
            float sc = __expf(m - mn);
            float p = __expf(alpha - mn);
            s = s * sc + p;
            acc.x = acc.x * sc + p * vv.x;
            acc.y = acc.y * sc + p * vv.y;
            acc.z = acc.z * sc + p * vv.z;
            acc.w = acc.w * sc + p * vv.w;
            m = mn;
            kv = kn; vv = vn;
        }
        float inv = 1.f / (s + 1e-16f);
        tot.x += acc.x * inv; tot.y += acc.y * inv;
        tot.z += acc.z * inv; tot.w += acc.w * inv;
    }
    *(float4*)(agg + (size_t)w * CDIM + lane * 4) = tot;
}

// ---------------- host orchestration -------------------------------------------
extern "C" void kernel_launch(void* const* d_in, const int* in_sizes, int n_in,
                              void* d_out, int out_size) {
    const float* x_paper  = (const float*)d_in[0];
    const float* x_author = (const float*)d_in[1];
    const float* lin_w = (const float*)d_in[2];
    const float* lin_b = (const float*)d_in[3];
    const float* k_w = (const float*)d_in[4];
    const float* k_b = (const float*)d_in[5];
    const float* q_w = (const float*)d_in[6];
    const float* q_b = (const float*)d_in[7];
    const float* v_w = (const float*)d_in[8];
    const float* v_b = (const float*)d_in[9];
    const float* a_w = (const float*)d_in[10];
    const float* a_b = (const float*)d_in[11];
    const float* skip  = (const float*)d_in[12];
    const float* a_rel = (const float*)d_in[13];
    const float* m_rel = (const float*)d_in[14];
    const float* p_rel = (const float*)d_in[15];
    const int* srcs[3] = {(const int*)d_in[16], (const int*)d_in[18], (const int*)d_in[20]};
    const int* dsts[3] = {(const int*)d_in[17], (const int*)d_in[19], (const int*)d_in[21]};
    int E[3] = {in_sizes[16], in_sizes[18], in_sizes[20]};

    static cudaStream_t s1 = nullptr;
    static cudaEvent_t ev[12];
    if (!s1) {
        cudaStreamCreateWithFlags(&s1, cudaStreamNonBlocking);
        for (int i = 0; i < 12; i++) cudaEventCreateWithFlags(&ev[i], cudaEventDisableTiming);
        cudaFuncSetAttribute(gemm_mma, cudaFuncAttributeMaxDynamicSharedMemorySize, SM_NEED);
    }
    cudaStream_t s0 = 0;
    int evi = 0;
    auto forkTo1 = [&]() { cudaEventRecord(ev[evi], s0); cudaStreamWaitEvent(s1, ev[evi], 0); evi++; };
    auto joinTo0 = [&]() { cudaEventRecord(ev[evi], s1); cudaStreamWaitEvent(s0, ev[evi], 0); evi++; };

    void* p;
    float *xb[2], *qb, *krel, *vrel, *agg, *Wk, *Wv, *bk, *bv;
    uint32_t* wpack;
    int *rowptr[3], *csrc[3], *cnt, *bsum;
    cudaGetSymbolAddress(&p, g_x);    xb[0] = (float*)p; xb[1] = xb[0] + (size_t)(NP + NA) * CDIM;
    cudaGetSymbolAddress(&p, g_q);    qb    = (float*)p;
    cudaGetSymbolAddress(&p, g_krel); krel  = (float*)p;
    cudaGetSymbolAddress(&p, g_vrel); vrel  = (float*)p;
    cudaGetSymbolAddress(&p, g_agg);  agg   = (float*)p;
    cudaGetSymbolAddress(&p, g_Wk);   Wk    = (float*)p;
    cudaGetSymbolAddress(&p, g_Wv);   Wv    = (float*)p;
    cudaGetSymbolAddress(&p, g_bk);   bk    = (float*)p;
    cudaGetSymbolAddress(&p, g_bv);   bv    = (float*)p;
    cudaGetSymbolAddress(&p, g_wpack);wpack = (uint32_t*)p;
    cudaGetSymbolAddress(&p, g_rowptr);
    for (int r = 0; r < 3; r++) rowptr[r] = (int*)p + (size_t)r * (NP + 1);
    cudaGetSymbolAddress(&p, g_csrc);
    for (int r = 0; r < 3; r++) csrc[r] = (int*)p + (size_t)r * EMAX;
    cudaGetSymbolAddress(&p, g_cnt);  cnt  = (int*)p;
    cudaGetSymbolAddress(&p, g_bsum); bsum = (int*)p;

    auto slot = [&](int s) { return (const uint4*)(wpack + (size_t)s * SLOT_U32); };
    auto run_gemm = [&](cudaStream_t st, const float* A, TileArgs& ta, int nt, int M,
                        int aop, int eop, const float* xold, const float* sp) {
        gemm_mma<<<(M + 127) / 128, 512, SM_NEED, st>>>(A, ta, nt, M, aop, eop, xold, sp);
    };

    // ======== fork: CSR build entirely on s1 ========
    forkTo1();
    for (int r = 0; r < 3; r++) {
        int Nd = (r == 2) ? NA : NP;
        fill_i<<<(Nd + 255) / 256, 256, 0, s1>>>(cnt, 0, Nd);
        hist_k<<<(E[r] + 255) / 256, 256, 0, s1>>>(dsts[r], cnt, E[r]);
        int nb = (Nd + 4095) / 4096;
        scan1<<<nb, 256, 0, s1>>>(cnt, rowptr[r] + 1, bsum, Nd);
        scan2<<<1, 32, 0, s1>>>(bsum, nb);
        scan3<<<(Nd + 255) / 256, 256, 0, s1>>>(rowptr[r], bsum, cnt, Nd);
        csr_fill<<<(E[r] + 255) / 256, 256, 0, s1>>>(srcs[r], dsts[r], cnt, csrc[r], E[r]);
    }

    // ======== wrapper: dedicated slots 10/11 (never overwritten later) =========
    {
        PackSrc ps{};
        ps.w[0] = lin_w; ps.w[1] = lin_w + CC; ps.count = 2; ps.slot0 = 10;
        pack_weights<<<dim3(2, 8), 128, 0, s0>>>(ps, wpack);
        forkTo1();   // wrapper pack -> s1 author wrapper gemm
        TileArgs ta{};
        ta.wp[0] = slot(10); ta.bias[0] = lin_b; ta.out[0] = xb[0];
        run_gemm(s0, x_paper, ta, 1, NP, 0, 1, nullptr, nullptr);
        TileArgs tb{};
        tb.wp[0] = slot(11); tb.bias[0] = lin_b + CDIM; tb.out[0] = xb[0] + NPC;
        run_gemm(s1, x_author, tb, 1, NA, 0, 1, nullptr, nullptr);
    }

    int cur = 0;
    for (int l = 0; l < 2; l++) {
        build_comp<<<dim3(CDIM, 3), CDIM, 0, s0>>>(
            k_w + (size_t)l * 2 * CC, k_b + l * 2 * CDIM,
            v_w + (size_t)l * 2 * CC, v_b + l * 2 * CDIM,
            a_rel + (size_t)l * 3 * NH * 1024, m_rel + (size_t)l * 3 * NH * 1024,
            Wk, bk, Wv, bv);

        {
            PackSrc ps{};
            ps.w[0] = q_w + (size_t)(l * 2 + 0) * CC;
            ps.w[1] = q_w + (size_t)(l * 2 + 1) * CC;
            ps.w[2] = Wk;          ps.w[3] = Wv;
            ps.w[4] = Wk + 2 * CC; ps.w[5] = Wv + 2 * CC;
            ps.w[6] = Wk + CC;     ps.w[7] = Wv + CC;
            ps.w[8] = a_w + (size_t)(l * 2 + 0) * CC;
            ps.w[9] = a_w + (size_t)(l * 2 + 1) * CC;
            ps.count = 10; ps.slot0 = 0;
            pack_weights<<<dim3(10, 8), 128, 0, s0>>>(ps, wpack);
        }

        forkTo1();  // packs ready -> s1 author fused gemm

        // s1: author fused gemm: q_a | krel1 | vrel1
        {
            TileArgs ta{};
            ta.wp[0] = slot(1); ta.bias[0] = q_b + (l * 2 + 1) * CDIM; ta.out[0] = qb + NPC;
            ta.wp[1] = slot(6); ta.bias[1] = bk + CDIM;      ta.out[1] = krel + (size_t)NPC;
            ta.wp[2] = slot(7); ta.bias[2] = bv + CDIM;      ta.out[2] = vrel + (size_t)NPC;
            run_gemm(s1, xb[cur] + NPC, ta, 3, NA, 0, 0, nullptr, nullptr);
        }
        // s0: paper fused gemm: q_p | krel0 | vrel0 | krel2 | vrel2
        {
            TileArgs ta{};
            ta.wp[0] = slot(0); ta.bias[0] = q_b + (l * 2 + 0) * CDIM; ta.out[0] = qb;
            ta.wp[1] = slot(2); ta.bias[1] = bk;             ta.out[1] = krel;
            ta.wp[2] = slot(3); ta.bias[2] = bv;             ta.out[2] = vrel;
            ta.wp[3] = slot(4); ta.bias[3] = bk + 2 * CDIM;  ta.out[3] = krel + 2 * (size_t)NPC;
            ta.wp[4] = slot(5); ta.bias[4] = bv + 2 * CDIM;  ta.out[4] = vrel + 2 * (size_t)NPC;
            run_gemm(s0, xb[cur], ta, 5, NP, 0, 0, nullptr, nullptr);
        }

        // cross-sync: s0 needs author results (krel1/vrel1); s1 needs paper results (krel2/vrel2)
        joinTo0();   // author gemm -> s0
        forkTo1();   // paper gemm  -> s1

        // s0: paper gather; s1: author gather
        edge_gather<<<(NP * 32 + 255) / 256, 256, 0, s0>>>(
            qb, agg, NP, 2,
            krel, vrel, rowptr[0], csrc[0], p_rel + (size_t)(l * 3 + 0) * NH,
            krel + (size_t)NPC, vrel + (size_t)NPC, rowptr[1], csrc[1],
            p_rel + (size_t)(l * 3 + 1) * NH);
        edge_gather<<<(NA * 32 + 255) / 256, 256, 0, s1>>>(
            qb + NPC, agg + NPC, NA, 1,
            krel + 2 * (size_t)NPC, vrel + 2 * (size_t)NPC, rowptr[2], csrc[2],
            p_rel + (size_t)(l * 3 + 2) * NH,
            nullptr, nullptr, nullptr, nullptr, nullptr);

        // out-projections
        {
            float* outp = (l == 1) ? (float*)d_out : xb[1 - cur];
            TileArgs ta{};
            ta.wp[0] = slot(8); ta.bias[0] = a_b + (l * 2 + 0) * CDIM; ta.out[0] = outp;
            run_gemm(s0, agg, ta, 1, NP, 1, 2, xb[cur], skip + l * 2 + 0);
        }
        {
            float* outp = ((l == 1) ? (float*)d_out : xb[1 - cur]) + NPC;
            TileArgs ta{};
            ta.wp[0] = slot(9); ta.bias[0] = a_b + (l * 2 + 1) * CDIM; ta.out[0] = outp;
            run_gemm(s1, agg + NPC, ta, 1, NA, 1, 2, xb[cur] + NPC, skip + l * 2 + 1);
        }

        joinTo0();   // layer end: all s1 work visible to s0
        cur = 1 - cur;
    }
}

// round 7
// speedup vs baseline: 2.8226x; 1.2336x over previous
#include <cuda_runtime.h>
#include <cuda_fp16.h>
#include <math.h>
#include <stdint.h>

#define NP 100000
#define NA 50000
#define CDIM 128
#define CC (CDIM*CDIM)
#define NH 4
#define NPC (NP*CDIM)
#define EMAX 300000

#define PITCH 136                 // fp16 per row in staged images
#define PITCHB 272                // bytes
#define A_IMG 17408               // 64 rows * 272B  (per A image)
#define B_IMG 34816               // 128 rows * 272B (B hi image)
#define SLOT_U32 8704             // B image = 8704 u32 per slot
#define NSLOT 22                  // 0-9 layer0, 10-19 layer1, 20-21 wrapper

// ---------------- scratch (device globals) -----------------------------------
__device__ float g_x[2][(NP+NA)*CDIM];
__device__ float g_q[(NP+NA)*CDIM];
__device__ float g_krel[3][NPC];
__device__ float g_vrel[3][NPC];
__device__ float g_agg[(NP+NA)*CDIM];
__device__ float g_Wk[2][3][CC];
__device__ float g_Wv[2][3][CC];
__device__ float g_bk[2][3][CDIM];
__device__ float g_bv[2][3][CDIM];
__device__ uint32_t g_wpack[NSLOT][SLOT_U32];
__device__ int g_rowptr[3][NP+1];
__device__ int g_csrc[3][EMAX];
__device__ int g_cnt[NP];
__device__ int g_bsum[64];

// ---------------- small helpers ----------------------------------------------
__device__ __forceinline__ float gelu_f(float x) {
    return 0.5f * x * (1.0f + erff(x * 0.7071067811865476f));
}
__global__ void fill_i(int* __restrict__ p, int v, int n) {
    int i = blockIdx.x * blockDim.x + threadIdx.x;
    if (i < n) p[i] = v;
}
__global__ void hist_k(const int* __restrict__ dst, int* __restrict__ cnt, int E) {
    int i = blockIdx.x * blockDim.x + threadIdx.x;
    if (i < E) atomicAdd(&cnt[dst[i]], 1);
}
__global__ void scan1(const int* __restrict__ cnt, int* __restrict__ rp1,
                      int* __restrict__ bsum, int n) {
    __shared__ int sm[256];
    int base = blockIdx.x * 4096;
    int idx0 = base + threadIdx.x * 16;
    int v[16]; int t = 0;
#pragma unroll
    for (int j = 0; j < 16; j++) { int ix = idx0 + j; v[j] = (ix < n) ? cnt[ix] : 0; t += v[j]; }
    sm[threadIdx.x] = t;
    __syncthreads();
    for (int off = 1; off < 256; off <<= 1) {
        int x = 0;
        if ((int)threadIdx.x >= off) x = sm[threadIdx.x - off];
        __syncthreads();
        if ((int)threadIdx.x >= off) sm[threadIdx.x] += x;
        __syncthreads();
    }
    int run = sm[threadIdx.x] - t;
#pragma unroll
    for (int j = 0; j < 16; j++) { run += v[j]; int ix = idx0 + j; if (ix < n) rp1[ix] = run; }
    if (threadIdx.x == 255) bsum[blockIdx.x] = sm[255];
}
__global__ void scan2(int* __restrict__ bsum, int nb) {
    int tid = threadIdx.x;
    int orig = (tid < nb) ? bsum[tid] : 0;
    int v = orig;
    for (int off = 1; off < 32; off <<= 1) {
        int x = __shfl_up_sync(0xffffffffu, v, off);
        if (tid >= off) v += x;
    }
    if (tid < nb) bsum[tid] = v - orig;
}
__global__ void scan3(int* __restrict__ rowptr, const int* __restrict__ bsum,
                      int* __restrict__ cursor, int n) {
    int i = blockIdx.x * blockDim.x + threadIdx.x;
    if (i < n) {
        int val = rowptr[i + 1] + bsum[i >> 12];
        rowptr[i + 1] = val;
        if (i + 1 < n) cursor[i + 1] = val;
    }
    if (i == 0) { rowptr[0] = 0; cursor[0] = 0; }
}
__global__ void csr_fill(const int* __restrict__ src, const int* __restrict__ dst,
                         int* __restrict__ cursor, int* __restrict__ csrc, int E) {
    int i = blockIdx.x * blockDim.x + threadIdx.x;
    if (i >= E) return;
    int pos = atomicAdd(&cursor[dst[i]], 1);
    csrc[pos] = src[i];
}

// ---------------- PTX helpers -------------------------------------------------
__device__ __forceinline__ uint32_t smem_u32(const void* p) {
    uint32_t a;
    asm("{ .reg .u64 t; cvta.to.shared.u64 t, %1; cvt.u32.u64 %0, t; }" : "=r"(a) : "l"(p));
    return a;
}
__device__ __forceinline__ uint32_t pk_h2(__half a, __half b) {
    __half2 t = __halves2half2(a, b);
    return *reinterpret_cast<uint32_t*>(&t);
}
__device__ __forceinline__ void ldsm4(uint32_t* r, uint32_t addr) {
    asm volatile("ldmatrix.sync.aligned.m8n8.x4.shared.b16 {%0,%1,%2,%3}, [%4];"
        : "=r"(r[0]), "=r"(r[1]), "=r"(r[2]), "=r"(r[3]) : "r"(addr));
}
__device__ __forceinline__ void mma16816(float* c, const uint32_t* a, const uint32_t* b) {
    asm volatile("mma.sync.aligned.m16n8k16.row.col.f32.f16.f16.f32 "
        "{%0,%1,%2,%3}, {%4,%5,%6,%7}, {%8,%9}, {%0,%1,%2,%3};"
        : "+f"(c[0]), "+f"(c[1]), "+f"(c[2]), "+f"(c[3])
        : "r"(a[0]), "r"(a[1]), "r"(a[2]), "r"(a[3]), "r"(b[0]), "r"(b[1]));
}
__device__ __forceinline__ void cp16(uint32_t dst, const void* src) {
    asm volatile("cp.async.cg.shared.global [%0], [%1], 16;" :: "r"(dst), "l"(src));
}

// ---------------- weight packing: fp32 -> pitched fp16 (hi only) ---------------
struct PackSrc { const float* w[NSLOT]; int count; };
__global__ void pack_weights(PackSrc ps, uint32_t* dstbase) {
    int m = blockIdx.x;
    if (m >= ps.count) return;
    const float* W = ps.w[m];
    uint32_t* hi = dstbase + (size_t)m * SLOT_U32;
    int n = threadIdx.x;
    int k0 = blockIdx.y * 16;
    for (int k = k0; k < k0 + 16; k += 2) {
        hi[n * (PITCH / 2) + (k >> 1)] =
            pk_h2(__float2half_rn(W[k * 128 + n]), __float2half_rn(W[(k + 1) * 128 + n]));
    }
}

// ---------------- composite relation weights (both layers) ---------------------
__global__ void build_comp(const float* __restrict__ kw0, const float* __restrict__ kb0,
                           const float* __restrict__ vw0, const float* __restrict__ vb0,
                           const float* __restrict__ arel0, const float* __restrict__ mrel0,
                           float* __restrict__ Wk0, float* __restrict__ bk0,
                           float* __restrict__ Wv0, float* __restrict__ bv0) {
    int c = blockIdx.x, r = blockIdx.y, l = blockIdx.z, j = threadIdx.x;
    const float* kw = kw0 + (size_t)l * 2 * CC;
    const float* kb = kb0 + l * 2 * CDIM;
    const float* vw = vw0 + (size_t)l * 2 * CC;
    const float* vb = vb0 + l * 2 * CDIM;
    const float* arel = arel0 + (size_t)l * 3 * NH * 1024;
    const float* mrel = mrel0 + (size_t)l * 3 * NH * 1024;
    float* Wk = Wk0 + (size_t)l * 3 * CC;
    float* Wv = Wv0 + (size_t)l * 3 * CC;
    float* bk = bk0 + l * 3 * CDIM;
    float* bv = bv0 + l * 3 * CDIM;
    int st = (r == 1) ? 1 : 0;
    int h = j >> 5, e = j & 31;
    const float* kwp = kw + ((size_t)st * CDIM + c) * CDIM + h * 32;
    const float* vwp = vw + ((size_t)st * CDIM + c) * CDIM + h * 32;
    const float* ap  = arel + (size_t)(r * NH + h) * 1024 + e;
    const float* mp  = mrel + (size_t)(r * NH + h) * 1024 + e;
    float sk = 0.f, sv = 0.f;
#pragma unroll
    for (int d = 0; d < 32; d++) {
        sk += kwp[d] * ap[d * 32];
        sv += vwp[d] * mp[d * 32];
    }
    Wk[(size_t)r * CC + (size_t)c * CDIM + j] = sk;
    Wv[(size_t)r * CC + (size_t)c * CDIM + j] = sv;
    if (c == 0) {
        float bks = 0.f, bvs = 0.f;
        const float* kbp = kb + st * CDIM + h * 32;
        const float* vbp = vb + st * CDIM + h * 32;
#pragma unroll
        for (int d = 0; d < 32; d++) {
            bks += kbp[d] * ap[d * 32];
            bvs += vbp[d] * mp[d * 32];
        }
        bk[r * CDIM + j] = bks;
        bv[r * CDIM + j] = bvs;
    }
}

// ---------------- tensor-core GEMM: fp16 2-term split, M-tile 64, 2 CTA/SM ----
struct TileArgs {
    const uint4* wp[5];
    const float* bias[5];
    float*       out[5];
};

#define SM_A_HI  0
#define SM_A_LO  A_IMG
#define SM_B(b)  (2*A_IMG + (b)*B_IMG)
#define SM_NEED  (2*A_IMG + 2*B_IMG)     // 104448 bytes -> 2 CTAs/SM

__device__ __forceinline__ void prefetch_B(uint32_t dstb, const uint4* src, int tid) {
#pragma unroll
    for (int i = 0; i < 8; i++) cp16(dstb + (uint32_t)(i * 256 + tid) * 16, src + i * 256 + tid);
    if (tid < 128) cp16(dstb + (uint32_t)(2048 + tid) * 16, src + 2048 + tid);
    asm volatile("cp.async.commit_group;" ::: "memory");
}

__global__ void __launch_bounds__(256, 2)
gemm_mma(const float* __restrict__ A, TileArgs ta, int ntiles, int M,
         int aop, int eop, const float* __restrict__ xold, const float* __restrict__ skipp) {
    extern __shared__ char sm[];
    uint32_t sb = smem_u32(sm);
    int tid = threadIdx.x, lane = tid & 31, wid = tid >> 5;
    int wm = wid & 1, wn = wid >> 1;           // 2 m-warps x 4 n-warps (32x32 per warp)
    int rowBase = blockIdx.x * 64;

    prefetch_B(sb + SM_B(0), ta.wp[0], tid);

    // ---- stage A: fp32 -> gelu? -> fp16 hi/lo, pitched (64 rows) ----
#pragma unroll 4
    for (int it = 0; it < 8; it++) {
        int f = it * 256 + tid;                // 2048 float4 chunks
        int m = f >> 5, k = (f & 31) << 2;
        int row = rowBase + m;
        float4 v = make_float4(0.f, 0.f, 0.f, 0.f);
        if (row < M) v = *(const float4*)(A + (size_t)row * CDIM + k);
        if (aop) { v.x = gelu_f(v.x); v.y = gelu_f(v.y); v.z = gelu_f(v.z); v.w = gelu_f(v.w); }
        __half h0 = __float2half_rn(v.x), h1 = __float2half_rn(v.y);
        __half h2 = __float2half_rn(v.z), h3 = __float2half_rn(v.w);
        float r0 = v.x - __half2float(h0), r1 = v.y - __half2float(h1);
        float r2 = v.z - __half2float(h2), r3 = v.w - __half2float(h3);
        uint32_t off = (uint32_t)(m * PITCHB + k * 2);
        *(uint2*)(sm + SM_A_HI + off) = make_uint2(pk_h2(h0, h1), pk_h2(h2, h3));
        *(uint2*)(sm + SM_A_LO + off) = make_uint2(
            pk_h2(__float2half_rn(r0), __float2half_rn(r1)),
            pk_h2(__float2half_rn(r2), __float2half_rn(r3)));
    }

    int aRow = wm * 32 + (lane & 15);
    uint32_t aKoff = (lane & 16) ? 16u : 0u;
    uint32_t aBaseHi = sb + SM_A_HI + aRow * PITCHB + aKoff;
    uint32_t aBaseLo = aBaseHi + A_IMG;
    int bN = wn * 32 + (lane & 7) + ((lane & 16) ? 8 : 0);
    uint32_t bKoff = (lane & 8) ? 16u : 0u;
    uint32_t bOff = bN * PITCHB + bKoff;

    float skv = 0.f;
    if (eop == 2) skv = 1.f / (1.f + expf(-*skipp));
    int g = lane >> 2, tg = lane & 3;

    for (int b = 0; b < ntiles; b++) {
        if (b + 1 < ntiles) {
            prefetch_B(sb + SM_B((b + 1) & 1), ta.wp[b + 1], tid);
            asm volatile("cp.async.wait_group 1;" ::: "memory");
        } else {
            asm volatile("cp.async.wait_group 0;" ::: "memory");
        }
        __syncthreads();

        float acc[2][4][4];
#pragma unroll
        for (int i = 0; i < 2; i++)
#pragma unroll
            for (int j = 0; j < 4; j++)
#pragma unroll
                for (int q = 0; q < 4; q++) acc[i][j][q] = 0.f;

        uint32_t aHi = aBaseHi, aLo = aBaseLo, bHi = sb + SM_B(b & 1) + bOff;
#pragma unroll
        for (int ks = 0; ks < 8; ks++) {
            uint32_t ah[2][4], al[2][4], bh[2][4];
            ldsm4(ah[0], aHi); ldsm4(ah[1], aHi + 16 * PITCHB);
            ldsm4(al[0], aLo); ldsm4(al[1], aLo + 16 * PITCHB);
            ldsm4(bh[0], bHi); ldsm4(bh[1], bHi + 16 * PITCHB);
#pragma unroll
            for (int i = 0; i < 2; i++)
#pragma unroll
                for (int j = 0; j < 4; j++) {
                    const uint32_t* bp = &bh[j >> 1][(j & 1) * 2];
                    mma16816(acc[i][j], ah[i], bp);
                    mma16816(acc[i][j], al[i], bp);
                }
            aHi += 32; aLo += 32; bHi += 32;
        }
        __syncthreads();

        const float* bias = ta.bias[b];
        float* out = ta.out[b];
#pragma unroll
        for (int i = 0; i < 2; i++) {
            int r0 = rowBase + wm * 32 + i * 16 + g;
#pragma unroll
            for (int j = 0; j < 4; j++) {
                int col = wn * 32 + j * 8 + tg * 2;
                float b0 = bias[col], b1 = bias[col + 1];
#pragma unroll
                for (int half = 0; half < 2; half++) {
                    int row = r0 + half * 8;
                    if (row >= M) continue;
                    float v0 = acc[i][j][half * 2 + 0] + b0;
                    float v1 = acc[i][j][half * 2 + 1] + b1;
                    if (eop == 1) {
                        v0 = fmaxf(v0, 0.f); v1 = fmaxf(v1, 0.f);
                    } else if (eop == 2) {
                        float2 xo = *(const float2*)(xold + (size_t)row * CDIM + col);
                        v0 = skv * v0 + (1.f - skv) * xo.x;
                        v1 = skv * v1 + (1.f - skv) * xo.y;
                    }
                    *(float2*)(out + (size_t)row * CDIM + col) = make_float2(v0, v1);
                }
            }
        }
    }
}

// ---------------- edge phase: CSR gather + online softmax (pipelined) ----------
__global__ void __launch_bounds__(256)
edge_gather(const float* __restrict__ q, float* __restrict__ agg, int N, int nrel,
            const float* __restrict__ kr0, const float* __restrict__ vr0,
            const int* __restrict__ rp0, const int* __restrict__ cs0,
            const float* __restrict__ pr0,
            const float* __restrict__ kr1, const float* __restrict__ vr1,
            const int* __restrict__ rp1, const int* __restrict__ cs1,
            const float* __restrict__ pr1) {
    int w = (blockIdx.x * blockDim.x + threadIdx.x) >> 5;
    if (w >= N) return;
    int lane = threadIdx.x & 31;
    int h = lane >> 3;
    float4 qv = *(const float4*)(q + (size_t)w * CDIM + lane * 4);
    float4 tot = make_float4(0.f, 0.f, 0.f, 0.f);
    for (int rel = 0; rel < nrel; rel++) {
        const float* kr = rel ? kr1 : kr0;
        const float* vr = rel ? vr1 : vr0;
        const int* rp = rel ? rp1 : rp0;
        const int* cs = rel ? cs1 : cs0;
        const float* prl = rel ? pr1 : pr0;
        float pscale = prl[h] * 0.17677669529663687f;
        int beg = rp[w], end = rp[w + 1];
        float m = -INFINITY, s = 0.f;
        float4 acc = make_float4(0.f, 0.f, 0.f, 0.f);
        float4 kv, vv;
        if (beg < end) {
            int sidx = cs[beg];
            kv = *(const float4*)(kr + (size_t)sidx * CDIM + lane * 4);
            vv = *(const float4*)(vr + (size_t)sidx * CDIM + lane * 4);
        }
        for (int e = beg; e < end; e++) {
            float4 kn, vn;
            if (e + 1 < end) {
                int sn = cs[e + 1];
                kn = *(const float4*)(kr + (size_t)sn * CDIM + lane * 4);
                vn = *(const float4*)(vr + (size_t)sn * CDIM + lane * 4);
            }
            float dot = qv.x * kv.x + qv.y * kv.y + qv.z * kv.z + qv.w * kv.w;
            dot += __shfl_xor_sync(0xffffffffu, dot, 1);
            dot += __shfl_xor_sync(0xffffffffu, dot, 2);
            dot += __shfl_xor_sync(0xffffffffu, dot, 4);
            float alpha = dot * pscale;
            float mn = fmaxf(m, alpha);
            float sc = __expf(m - mn);
            float p = __expf(alpha - mn);
            s = s * sc + p;
            acc.x = acc.x * sc + p * vv.x;
            acc.y = acc.y * sc + p * vv.y;
            acc.z = acc.z * sc + p * vv.z;
            acc.w = acc.w * sc + p * vv.w;
            m = mn;
            kv = kn; vv = vn;
        }
        float inv = 1.f / (s + 1e-16f);
        tot.x += acc.x * inv; tot.y += acc.y * inv;
        tot.z += acc.z * inv; tot.w += acc.w * inv;
    }
    *(float4*)(agg + (size_t)w * CDIM + lane * 4) = tot;
}

// ---------------- host orchestration -------------------------------------------
extern "C" void kernel_launch(void* const* d_in, const int* in_sizes, int n_in,
                              void* d_out, int out_size) {
    const float* x_paper  = (const float*)d_in[0];
    const float* x_author = (const float*)d_in[1];
    const float* lin_w = (const float*)d_in[2];
    const float* lin_b = (const float*)d_in[3];
    const float* k_w = (const float*)d_in[4];
    const float* k_b = (const float*)d_in[5];
    const float* q_w = (const float*)d_in[6];
    const float* q_b = (const float*)d_in[7];
    const float* v_w = (const float*)d_in[8];
    const float* v_b = (const float*)d_in[9];
    const float* a_w = (const float*)d_in[10];
    const float* a_b = (const float*)d_in[11];
    const float* skip  = (const float*)d_in[12];
    const float* a_rel = (const float*)d_in[13];
    const float* m_rel = (const float*)d_in[14];
    const float* p_rel = (const float*)d_in[15];
    const int* srcs[3] = {(const int*)d_in[16], (const int*)d_in[18], (const int*)d_in[20]};
    const int* dsts[3] = {(const int*)d_in[17], (const int*)d_in[19], (const int*)d_in[21]};
    int E[3] = {in_sizes[16], in_sizes[18], in_sizes[20]};

    static cudaStream_t s1 = nullptr;
    static cudaEvent_t ev[12];
    if (!s1) {
        cudaStreamCreateWithFlags(&s1, cudaStreamNonBlocking);
        for (int i = 0; i < 12; i++) cudaEventCreateWithFlags(&ev[i], cudaEventDisableTiming);
        cudaFuncSetAttribute(gemm_mma, cudaFuncAttributeMaxDynamicSharedMemorySize, SM_NEED);
    }
    cudaStream_t s0 = 0;
    int evi = 0;
    auto forkTo1 = [&]() { cudaEventRecord(ev[evi], s0); cudaStreamWaitEvent(s1, ev[evi], 0); evi++; };
    auto joinTo0 = [&]() { cudaEventRecord(ev[evi], s1); cudaStreamWaitEvent(s0, ev[evi], 0); evi++; };

    void* p;
    float *xb[2], *qb, *krel, *vrel, *agg, *Wk, *Wv, *bk, *bv;
    uint32_t* wpack;
    int *rowptr[3], *csrc[3], *cnt, *bsum;
    cudaGetSymbolAddress(&p, g_x);    xb[0] = (float*)p; xb[1] = xb[0] + (size_t)(NP + NA) * CDIM;
    cudaGetSymbolAddress(&p, g_q);    qb    = (float*)p;
    cudaGetSymbolAddress(&p, g_krel); krel  = (float*)p;
    cudaGetSymbolAddress(&p, g_vrel); vrel  = (float*)p;
    cudaGetSymbolAddress(&p, g_agg);  agg   = (float*)p;
    cudaGetSymbolAddress(&p, g_Wk);   Wk    = (float*)p;
    cudaGetSymbolAddress(&p, g_Wv);   Wv    = (float*)p;
    cudaGetSymbolAddress(&p, g_bk);   bk    = (float*)p;
    cudaGetSymbolAddress(&p, g_bv);   bv    = (float*)p;
    cudaGetSymbolAddress(&p, g_wpack);wpack = (uint32_t*)p;
    cudaGetSymbolAddress(&p, g_rowptr);
    for (int r = 0; r < 3; r++) rowptr[r] = (int*)p + (size_t)r * (NP + 1);
    cudaGetSymbolAddress(&p, g_csrc);
    for (int r = 0; r < 3; r++) csrc[r] = (int*)p + (size_t)r * EMAX;
    cudaGetSymbolAddress(&p, g_cnt);  cnt  = (int*)p;
    cudaGetSymbolAddress(&p, g_bsum); bsum = (int*)p;

    auto slot = [&](int s) { return (const uint4*)(wpack + (size_t)s * SLOT_U32); };
    auto run_gemm = [&](cudaStream_t st, const float* A, TileArgs& ta, int nt, int M,
                        int aop, int eop, const float* xold, const float* sp) {
        gemm_mma<<<(M + 63) / 64, 256, SM_NEED, st>>>(A, ta, nt, M, aop, eop, xold, sp);
    };

    // ======== fork: CSR build entirely on s1 ========
    forkTo1();
    for (int r = 0; r < 3; r++) {
        int Nd = (r == 2) ? NA : NP;
        fill_i<<<(Nd + 255) / 256, 256, 0, s1>>>(cnt, 0, Nd);
        hist_k<<<(E[r] + 255) / 256, 256, 0, s1>>>(dsts[r], cnt, E[r]);
        int nb = (Nd + 4095) / 4096;
        scan1<<<nb, 256, 0, s1>>>(cnt, rowptr[r] + 1, bsum, Nd);
        scan2<<<1, 32, 0, s1>>>(bsum, nb);
        scan3<<<(Nd + 255) / 256, 256, 0, s1>>>(rowptr[r], bsum, cnt, Nd);
        csr_fill<<<(E[r] + 255) / 256, 256, 0, s1>>>(srcs[r], dsts[r], cnt, csrc[r], E[r]);
    }

    // ======== s0: build both layers' composite weights + pack ALL 22 slots =====
    build_comp<<<dim3(CDIM, 3, 2), CDIM, 0, s0>>>(k_w, k_b, v_w, v_b, a_rel, m_rel,
                                                  Wk, bk, Wv, bv);
    {
        PackSrc ps{};
        for (int l = 0; l < 2; l++) {
            int base = l * 10;
            ps.w[base + 0] = q_w + (size_t)(l * 2 + 0) * CC;
            ps.w[base + 1] = q_w + (size_t)(l * 2 + 1) * CC;
            ps.w[base + 2] = Wk + (size_t)(l * 3 + 0) * CC;
            ps.w[base + 3] = Wv + (size_t)(l * 3 + 0) * CC;
            ps.w[base + 4] = Wk + (size_t)(l * 3 + 2) * CC;
            ps.w[base + 5] = Wv + (size_t)(l * 3 + 2) * CC;
            ps.w[base + 6] = Wk + (size_t)(l * 3 + 1) * CC;
            ps.w[base + 7] = Wv + (size_t)(l * 3 + 1) * CC;
            ps.w[base + 8] = a_w + (size_t)(l * 2 + 0) * CC;
            ps.w[base + 9] = a_w + (size_t)(l * 2 + 1) * CC;
        }
        ps.w[20] = lin_w; ps.w[21] = lin_w + CC;
        ps.count = NSLOT;
        pack_weights<<<dim3(NSLOT, 8), 128, 0, s0>>>(ps, wpack);
    }

    // ======== wrapper GEMMs: paper on s0, author on s1 (after pack) ============
    forkTo1();
    {
        TileArgs ta{};
        ta.wp[0] = slot(20); ta.bias[0] = lin_b; ta.out[0] = xb[0];
        run_gemm(s0, x_paper, ta, 1, NP, 0, 1, nullptr, nullptr);
        TileArgs tb{};
        tb.wp[0] = slot(21); tb.bias[0] = lin_b + CDIM; tb.out[0] = xb[0] + NPC;
        run_gemm(s1, x_author, tb, 1, NA, 0, 1, nullptr, nullptr);
    }

    int cur = 0;
    for (int l = 0; l < 2; l++) {
        int sl = l * 10;
        const float* bkL = bk + l * 3 * CDIM;
        const float* bvL = bv + l * 3 * CDIM;

        // s1: author fused gemm: q_a | krel1 | vrel1
        {
            TileArgs ta{};
            ta.wp[0] = slot(sl + 1); ta.bias[0] = q_b + (l * 2 + 1) * CDIM; ta.out[0] = qb + NPC;
            ta.wp[1] = slot(sl + 6); ta.bias[1] = bkL + CDIM;     ta.out[1] = krel + (size_t)NPC;
            ta.wp[2] = slot(sl + 7); ta.bias[2] = bvL + CDIM;     ta.out[2] = vrel + (size_t)NPC;
            run_gemm(s1, xb[cur] + NPC, ta, 3, NA, 0, 0, nullptr, nullptr);
        }
        // s0: paper fused gemm: q_p | krel0 | vrel0 | krel2 | vrel2
        {
            TileArgs ta{};
            ta.wp[0] = slot(sl + 0); ta.bias[0] = q_b + (l * 2 + 0) * CDIM; ta.out[0] = qb;
            ta.wp[1] = slot(sl + 2); ta.bias[1] = bkL;            ta.out[1] = krel;
            ta.wp[2] = slot(sl + 3); ta.bias[2] = bvL;            ta.out[2] = vrel;
            ta.wp[3] = slot(sl + 4); ta.bias[3] = bkL + 2 * CDIM; ta.out[3] = krel + 2 * (size_t)NPC;
            ta.wp[4] = slot(sl + 5); ta.bias[4] = bvL + 2 * CDIM; ta.out[4] = vrel + 2 * (size_t)NPC;
            run_gemm(s0, xb[cur], ta, 5, NP, 0, 0, nullptr, nullptr);
        }

        joinTo0();   // author gemm results (krel1/vrel1) -> s0 gather
        forkTo1();   // paper gemm results (krel2/vrel2)  -> s1 gather

        edge_gather<<<(NP * 32 + 255) / 256, 256, 0, s0>>>(
            qb, agg, NP, 2,
            krel, vrel, rowptr[0], csrc[0], p_rel + (size_t)(l * 3 + 0) * NH,
            krel + (size_t)NPC, vrel + (size_t)NPC, rowptr[1], csrc[1],
            p_rel + (size_t)(l * 3 + 1) * NH);
        edge_gather<<<(NA * 32 + 255) / 256, 256, 0, s1>>>(
            qb + NPC, agg + NPC, NA, 1,
            krel + 2 * (size_t)NPC, vrel + 2 * (size_t)NPC, rowptr[2], csrc[2],
            p_rel + (size_t)(l * 3 + 2) * NH,
            nullptr, nullptr, nullptr, nullptr, nullptr);

        {
            float* outp = (l == 1) ? (float*)d_out : xb[1 - cur];
            TileArgs ta{};
            ta.wp[0] = slot(sl + 8); ta.bias[0] = a_b + (l * 2 + 0) * CDIM; ta.out[0] = outp;
            run_gemm(s0, agg, ta, 1, NP, 1, 2, xb[cur], skip + l * 2 + 0);
        }
        {
            float* outp = ((l == 1) ? (float*)d_out : xb[1 - cur]) + NPC;
            TileArgs ta{};
            ta.wp[0] = slot(sl + 9); ta.bias[0] = a_b + (l * 2 + 1) * CDIM; ta.out[0] = outp;
            run_gemm(s1, agg + NPC, ta, 1, NA, 1, 2, xb[cur] + NPC, skip + l * 2 + 1);
        }

        // layer boundary: order both directions (next layer's gemms overwrite
        // qb/krel/vrel that this layer's gathers on the other stream still read)
        joinTo0();
        if (l == 0) forkTo1();
        cur = 1 - cur;
    }
}